// round 10
// baseline (speedup 1.0000x reference)
#include <cuda_runtime.h>
#include <cuda_fp16.h>
#include <cstddef>
#include <cstdint>

// Problem constants
#define B_   4
#define N_   16384
#define E_   131072
#define HID_ 128
#define H_   8
#define D_   16
#define M_   (B_ * N_)   // 65536 flattened rows
#define HID3 384

// ---------------------------------------------------------------------------
// Scratch (device globals; no allocations allowed)
// ---------------------------------------------------------------------------
__device__ __half g_h16[(size_t)M_ * HID_];          // h in fp16 (QKV A)
__device__ __half g_QKV16[(size_t)M_ * HID3];        // Q|K|V packed per row, fp16
__device__ float  g_denom[(size_t)B_ * N_ * H_];
__device__ float  g_attn[(size_t)M_ * HID_];         // unnormalized Σ p·V
__device__ __half g_attn16[(size_t)M_ * HID_];       // normalized attn, fp16
__device__ float  g_proj[(size_t)M_ * HID_];         // Wo out, later ff2 out
__device__ float  g_hmid[(size_t)M_ * HID_];
__device__ __half g_hmid16[(size_t)M_ * HID_];       // LN1 out, fp16 (ff1 A)
__device__ __half g_ff16[(size_t)M_ * 2 * HID_];     // ff1 output (fp16)
__device__ __half g_w16[49152 + 16384 + 32768 + 32768]; // packed fp16 weights

#define W16_QKV 0
#define W16_WO  49152
#define W16_FF1 65536
#define W16_FF2 98304

// ---------------------------------------------------------------------------
// Helpers
// ---------------------------------------------------------------------------
__device__ __forceinline__ void cp_async16(uint32_t s, const void* g) {
    asm volatile("cp.async.cg.shared.global [%0], [%1], 16;" :: "r"(s), "l"(g));
}

__device__ __forceinline__ void ldsm_x4(uint32_t* r, uint32_t addr) {
    asm volatile("ldmatrix.sync.aligned.m8n8.x4.shared.b16 {%0,%1,%2,%3}, [%4];"
                 : "=r"(r[0]), "=r"(r[1]), "=r"(r[2]), "=r"(r[3]) : "r"(addr));
}
__device__ __forceinline__ void ldsm_x4_t(uint32_t* r, uint32_t addr) {
    asm volatile("ldmatrix.sync.aligned.m8n8.x4.trans.shared.b16 {%0,%1,%2,%3}, [%4];"
                 : "=r"(r[0]), "=r"(r[1]), "=r"(r[2]), "=r"(r[3]) : "r"(addr));
}
__device__ __forceinline__ void mma_f16(float* d, const uint32_t* a, uint32_t b0, uint32_t b1) {
    asm volatile(
        "mma.sync.aligned.m16n8k16.row.col.f32.f16.f16.f32 "
        "{%0,%1,%2,%3}, {%4,%5,%6,%7}, {%8,%9}, {%0,%1,%2,%3};"
        : "+f"(d[0]), "+f"(d[1]), "+f"(d[2]), "+f"(d[3])
        : "r"(a[0]), "r"(a[1]), "r"(a[2]), "r"(a[3]), "r"(b0), "r"(b1));
}

// dot of 4 fp16 pairs (as uint2) in fp32
__device__ __forceinline__ float dot4h(uint2 qa, uint2 ka) {
    float2 q0 = __half22float2(*(__half2*)&qa.x);
    float2 q1 = __half22float2(*(__half2*)&qa.y);
    float2 k0 = __half22float2(*(__half2*)&ka.x);
    float2 k1 = __half22float2(*(__half2*)&ka.y);
    return q0.x * k0.x + q0.y * k0.y + q1.x * k1.x + q1.y * k1.y;
}

// ---------------------------------------------------------------------------
// Weight pack: fp32 -> fp16. Wqkv interleaved [128][384], rest linear.
// ---------------------------------------------------------------------------
__global__ void prep_w16_kernel(const float* __restrict__ Wq, const float* __restrict__ Wk,
                                const float* __restrict__ Wv, const float* __restrict__ Wo,
                                const float* __restrict__ ff1, const float* __restrict__ ff2,
                                __half* __restrict__ w16) {
    int idx = blockIdx.x * blockDim.x + threadIdx.x;
    if (idx < 49152) {
        int k = idx / HID3, j = idx % HID3;
        float v = (j < 128) ? Wq[k * 128 + j]
                : (j < 256) ? Wk[k * 128 + j - 128]
                            : Wv[k * 128 + j - 256];
        w16[W16_QKV + idx] = __float2half(v);
    } else if (idx < 49152 + 16384) {
        w16[idx] = __float2half(Wo[idx - 49152]);
    } else if (idx < 49152 + 16384 + 32768) {
        w16[idx] = __float2half(ff1[idx - 65536]);
    } else {
        w16[idx] = __float2half(ff2[idx - 98304]);
    }
}

// ---------------------------------------------------------------------------
// Init: denom = 0, attn = 0
// ---------------------------------------------------------------------------
__global__ void init_kernel(float* __restrict__ denom, float* __restrict__ attn) {
    size_t i = (size_t)blockIdx.x * blockDim.x + threadIdx.x;
    if (i < (size_t)B_ * N_ * H_) denom[i] = 0.0f;
    if (i < (size_t)M_ * HID_) attn[i] = 0.0f;
}

// ---------------------------------------------------------------------------
// f32 -> f16 convert (float4 per thread). If dnm != nullptr, divide by
// max(denom[row, col/16], 1e-6) first (attention normalization).
// ---------------------------------------------------------------------------
__global__ void __launch_bounds__(256)
cvt16_kernel(const float* __restrict__ in, __half* __restrict__ out,
             const float* __restrict__ dnm) {
    const size_t i = (size_t)blockIdx.x * blockDim.x + threadIdx.x; // over M_*HID_/4
    const int row = (int)(i >> 5);
    const int c = ((int)i & 31) * 4;
    float4 v = *(const float4*)(in + (size_t)row * HID_ + c);
    if (dnm) {
        const float dv = dnm[(size_t)row * H_ + (c >> 4)];
        const float inv = 1.0f / fmaxf(dv, 1e-6f);
        v.x *= inv; v.y *= inv; v.z *= inv; v.w *= inv;
    }
    uint2 o;
    *(__half2*)&o.x = __floats2half2_rn(v.x, v.y);
    *(__half2*)&o.y = __floats2half2_rn(v.z, v.w);
    *(uint2*)(out + (size_t)row * HID_ + c) = o;
}

// ---------------------------------------------------------------------------
// FP16 tensor-core GEMM: C[M, Nn] = A16[M, Kk] @ B16[Kk, Nn]
// CTA tile 128x128, TBK=64 double-buffered cp.async pipeline, 8 warps (4x2),
// warp tile 32x64, mma.m16n8k16 fp16->fp32, ldmatrix fragments.
// EPI: 1 = +bias (f32 out), 2 = +bias+relu (f16 out), 3 = none (f16 out)
// ---------------------------------------------------------------------------
#define TBM 128
#define TBN 128
#define TBK 64
#define AS2 72                          // halves per A smem row (144B stride)
#define BS2 136                         // halves per B smem row (272B stride)
#define A_H (TBM * AS2)                 // 9216 halves
#define B_H (TBK * BS2)                 // 8704 halves
#define BUF_H (A_H + B_H)               // 17920 halves = 35840 B
#define GEMM_SMEM_BYTES (2 * BUF_H * 2) // 71680 B

template <int EPI>
__global__ void __launch_bounds__(256, 2)
gemm_h(const __half* __restrict__ Ap, const __half* __restrict__ Bp,
       const float* __restrict__ bias, void* __restrict__ Cp,
       int Kk, int Nn) {
    extern __shared__ __half sm[];

    const int tid  = threadIdx.x;
    const int wid  = tid >> 5;
    const int lane = tid & 31;
    const int g = lane >> 2;      // 0..7
    const int q = lane & 3;       // 0..3
    const int warpM = wid & 3;    // rows: 32 each
    const int warpN = wid >> 2;   // cols: 64 each
    const int rowBase = blockIdx.y * TBM;
    const int colBase = blockIdx.x * TBN;

    const uint32_t smem_u32 = (uint32_t)__cvta_generic_to_shared(sm);

    float acc[2][8][4];
    #pragma unroll
    for (int mt = 0; mt < 2; mt++)
        #pragma unroll
        for (int nt = 0; nt < 8; nt++)
            #pragma unroll
            for (int i = 0; i < 4; i++) acc[mt][nt][i] = 0.0f;

    const int lrow = lane & 15;
    const int lcol = (lane >> 4) * 8;
    const int nch = Kk / TBK;

    auto prefetch = [&](int buf, int k0) {
        const uint32_t base = smem_u32 + (uint32_t)buf * (BUF_H * 2);
        // A chunk: 128 rows x 64 halves = 1024 x 16B
        #pragma unroll
        for (int i = 0; i < 4; i++) {
            int idx = tid + i * 256;
            int r   = idx >> 3;
            int c8  = (idx & 7) * 8;
            cp_async16(base + (uint32_t)(r * AS2 + c8) * 2,
                       Ap + (size_t)(rowBase + r) * Kk + k0 + c8);
        }
        // B chunk: 64 rows x 128 halves = 1024 x 16B
        const uint32_t bbase = base + A_H * 2;
        #pragma unroll
        for (int i = 0; i < 4; i++) {
            int idx = tid + i * 256;
            int r   = idx >> 4;
            int c8  = (idx & 15) * 8;
            cp_async16(bbase + (uint32_t)(r * BS2 + c8) * 2,
                       Bp + (size_t)(k0 + r) * Nn + colBase + c8);
        }
        asm volatile("cp.async.commit_group;");
    };

    prefetch(0, 0);

    for (int kc = 0; kc < nch; kc++) {
        if (kc + 1 < nch) {
            prefetch((kc + 1) & 1, (kc + 1) * TBK);
            asm volatile("cp.async.wait_group 1;");
        } else {
            asm volatile("cp.async.wait_group 0;");
        }
        __syncthreads();

        const uint32_t sbuf = smem_u32 + (uint32_t)(kc & 1) * (BUF_H * 2);
        const uint32_t sA = sbuf;
        const uint32_t sB = sbuf + A_H * 2;

        #pragma unroll
        for (int kk = 0; kk < 4; kk++) {
            uint32_t af[2][4];
            #pragma unroll
            for (int mt = 0; mt < 2; mt++)
                ldsm_x4(af[mt], sA + (uint32_t)((warpM * 32 + mt * 16 + lrow) * AS2
                                                + kk * 16 + lcol) * 2);
            uint32_t bf[4][4];
            #pragma unroll
            for (int n4 = 0; n4 < 4; n4++)
                ldsm_x4_t(bf[n4], sB + (uint32_t)((kk * 16 + lrow) * BS2
                                                  + warpN * 64 + n4 * 16 + lcol) * 2);
            #pragma unroll
            for (int mt = 0; mt < 2; mt++)
                #pragma unroll
                for (int nt = 0; nt < 8; nt++) {
                    const int n4 = nt >> 1, sel = (nt & 1) * 2;
                    mma_f16(acc[mt][nt], af[mt], bf[n4][sel], bf[n4][sel + 1]);
                }
        }
        __syncthreads();
    }

    // ---- epilogue ----
    #pragma unroll
    for (int mt = 0; mt < 2; mt++) {
        #pragma unroll
        for (int half = 0; half < 2; half++) {
            const int r = rowBase + warpM * 32 + mt * 16 + half * 8 + g;
            #pragma unroll
            for (int nt = 0; nt < 8; nt++) {
                const int c = colBase + warpN * 64 + nt * 8 + q * 2;
                float v0 = acc[mt][nt][half * 2 + 0];
                float v1 = acc[mt][nt][half * 2 + 1];
                if (EPI == 1 || EPI == 2) { v0 += bias[c]; v1 += bias[c + 1]; }
                if (EPI == 2) { v0 = fmaxf(v0, 0.0f); v1 = fmaxf(v1, 0.0f); }
                if (EPI >= 2) {
                    *(__half2*)((__half*)Cp + (size_t)r * Nn + c) = __floats2half2_rn(v0, v1);
                } else {
                    float2 o = {v0, v1};
                    *(float2*)((float*)Cp + (size_t)r * Nn + c) = o;
                }
            }
        }
    }
}

// ---------------------------------------------------------------------------
// Fused edge pass: logits -> p = exp -> denom += p, attn[dst] += p * V[src].
// FOUR edges per warp (max memory-level parallelism); lane -> head = lane/4,
// dv = lane%4. QKV fp16 packed per row: Q +0, K +128, V +256 (halves,
// stride HID3). No max pass (shift-invariant, O(1) logits); normalization
// deferred to the attn->fp16 convert pass.
// ---------------------------------------------------------------------------
__global__ void __launch_bounds__(256)
edge_attn_kernel(const __half* __restrict__ QKV,
                 const float* __restrict__ ef, const int* __restrict__ eidx,
                 const int* __restrict__ nE, const float* __restrict__ We,
                 float* __restrict__ denom, float* __restrict__ attn) {
    const int w = (blockIdx.x * blockDim.x + threadIdx.x) >> 5;
    const int lane = threadIdx.x & 31;
    const int b = w >> 15;              // E_/4 = 32768 warps per batch
    const int e0 = (w & 32767) * 4;
    const int ne = nE[b];
    if (e0 >= ne) return;
    const int cnt = min(4, ne - e0);

    const int head = lane >> 2;
    const int dv = lane & 3;
    const int hoff = head * D_ + dv * 4;

    const size_t ebase = (size_t)b * 2 * E_;
    const int4 srcs = *(const int4*)(eidx + ebase + e0);        // src e0..e0+3
    const int4 dsts = *(const int4*)(eidx + ebase + E_ + e0);   // dst e0..e0+3
    const int src[4] = {srcs.x, srcs.y, srcs.z, srcs.w};
    const int dst[4] = {dsts.x, dsts.y, dsts.z, dsts.w};

    // issue all gathers up-front (indices past cnt are still valid node ids)
    uint2 qv[4], kv[4], vv[4];
    #pragma unroll
    for (int i = 0; i < 4; i++) {
        const __half* qp = QKV + ((size_t)(b * N_ + dst[i])) * HID3 + hoff;
        const __half* kp = QKV + ((size_t)(b * N_ + src[i])) * HID3 + 128 + hoff;
        qv[i] = *(const uint2*)qp;
        kv[i] = *(const uint2*)kp;
        vv[i] = *(const uint2*)(kp + 128);
    }
    const float4 ef01 = *(const float4*)(ef + ((size_t)b * E_ + e0) * 2);
    const float4 ef23 = *(const float4*)(ef + ((size_t)b * E_ + e0) * 2 + 4);
    const float we0 = __ldg(We + head);
    const float we1 = __ldg(We + H_ + head);
    const float efe[4][2] = {{ef01.x, ef01.y}, {ef01.z, ef01.w},
                             {ef23.x, ef23.y}, {ef23.z, ef23.w}};

    float s[4];
    #pragma unroll
    for (int i = 0; i < 4; i++) s[i] = dot4h(qv[i], kv[i]);
    #pragma unroll
    for (int i = 0; i < 4; i++) {
        s[i] += __shfl_xor_sync(0xFFFFFFFFu, s[i], 1);
        s[i] += __shfl_xor_sync(0xFFFFFFFFu, s[i], 2);
    }

    #pragma unroll
    for (int i = 0; i < 4; i++) {
        if (i >= cnt) break;
        const float p = __expf(s[i] * 0.25f + efe[i][0] * we0 + efe[i][1] * we1);
        if (dv == 0)
            atomicAdd(denom + ((size_t)(b * N_ + dst[i])) * H_ + head, p);
        float2 a = __half22float2(*(__half2*)&vv[i].x);
        float2 c = __half22float2(*(__half2*)&vv[i].y);
        float* out = attn + ((size_t)(b * N_ + dst[i])) * HID_ + hoff;
        asm volatile("red.global.add.v4.f32 [%0], {%1, %2, %3, %4};"
                     :: "l"(out), "f"(p * a.x), "f"(p * a.y),
                        "f"(p * c.x), "f"(p * c.y) : "memory");
    }
}

// ---------------------------------------------------------------------------
// out = LayerNorm(x + res) * g + b (warp per 128-elem row).
// Optionally also writes fp16 copy (for the next GEMM's A operand).
// ---------------------------------------------------------------------------
__global__ void __launch_bounds__(256)
add_ln_kernel(const float* __restrict__ x, const float* __restrict__ res,
              const float* __restrict__ g, const float* __restrict__ bb,
              float* __restrict__ out, __half* __restrict__ out16) {
    const int row = (blockIdx.x * blockDim.x + threadIdx.x) >> 5;
    const int lane = threadIdx.x & 31;
    const size_t off = (size_t)row * HID_ + lane * 4;

    const float4 a = *(const float4*)(x + off);
    const float4 r = *(const float4*)(res + off);
    float4 v = {a.x + r.x, a.y + r.y, a.z + r.z, a.w + r.w};

    float sum = v.x + v.y + v.z + v.w;
    float sq  = v.x * v.x + v.y * v.y + v.z * v.z + v.w * v.w;
    #pragma unroll
    for (int s = 16; s; s >>= 1) {
        sum += __shfl_xor_sync(0xFFFFFFFFu, sum, s);
        sq  += __shfl_xor_sync(0xFFFFFFFFu, sq, s);
    }
    const float mean = sum * (1.0f / 128.0f);
    const float var  = sq * (1.0f / 128.0f) - mean * mean;
    const float rs   = rsqrtf(var + 1e-5f);

    const float4 gg = *(const float4*)(g + lane * 4);
    const float4 bv = *(const float4*)(bb + lane * 4);
    float4 o;
    o.x = (v.x - mean) * rs * gg.x + bv.x;
    o.y = (v.y - mean) * rs * gg.y + bv.y;
    o.z = (v.z - mean) * rs * gg.z + bv.z;
    o.w = (v.w - mean) * rs * gg.w + bv.w;
    *(float4*)(out + off) = o;
    if (out16) {
        uint2 h;
        *(__half2*)&h.x = __floats2half2_rn(o.x, o.y);
        *(__half2*)&h.y = __floats2half2_rn(o.z, o.w);
        *(uint2*)(out16 + off) = h;
    }
}

// ---------------------------------------------------------------------------
// Launch
// ---------------------------------------------------------------------------
extern "C" void kernel_launch(void* const* d_in, const int* in_sizes, int n_in,
                              void* d_out, int out_size) {
    const float* h    = (const float*)d_in[0];
    const float* ef   = (const float*)d_in[1];
    const int*   eidx = (const int*)d_in[2];
    const int*   nE   = (const int*)d_in[3];
    const float* Wq   = (const float*)d_in[4];
    const float* Wk   = (const float*)d_in[5];
    const float* Wv   = (const float*)d_in[6];
    const float* Wo   = (const float*)d_in[7];
    const float* bo   = (const float*)d_in[8];
    const float* We   = (const float*)d_in[9];
    const float* ln1g = (const float*)d_in[10];
    const float* ln1b = (const float*)d_in[11];
    const float* ln2g = (const float*)d_in[12];
    const float* ln2b = (const float*)d_in[13];
    const float* ff1  = (const float*)d_in[14];
    const float* b1   = (const float*)d_in[15];
    const float* ff2  = (const float*)d_in[16];
    const float* b2   = (const float*)d_in[17];
    float* out = (float*)d_out;

    float *dn, *attn, *proj, *hmid;
    __half *h16, *QKV16, *attn16, *hmid16, *ffb, *w16;
    cudaGetSymbolAddress((void**)&h16, g_h16);
    cudaGetSymbolAddress((void**)&QKV16, g_QKV16);
    cudaGetSymbolAddress((void**)&dn, g_denom);
    cudaGetSymbolAddress((void**)&attn, g_attn);
    cudaGetSymbolAddress((void**)&attn16, g_attn16);
    cudaGetSymbolAddress((void**)&proj, g_proj);
    cudaGetSymbolAddress((void**)&hmid, g_hmid);
    cudaGetSymbolAddress((void**)&hmid16, g_hmid16);
    cudaGetSymbolAddress((void**)&ffb, g_ff16);
    cudaGetSymbolAddress((void**)&w16, g_w16);

    static bool attr_done = false;
    if (!attr_done) {
        cudaFuncSetAttribute((const void*)gemm_h<1>, cudaFuncAttributeMaxDynamicSharedMemorySize, GEMM_SMEM_BYTES);
        cudaFuncSetAttribute((const void*)gemm_h<2>, cudaFuncAttributeMaxDynamicSharedMemorySize, GEMM_SMEM_BYTES);
        cudaFuncSetAttribute((const void*)gemm_h<3>, cudaFuncAttributeMaxDynamicSharedMemorySize, GEMM_SMEM_BYTES);
        attr_done = true;
    }

    // 0. weight pack (fp32 -> fp16), init accumulators, h -> fp16
    prep_w16_kernel<<<512, 256>>>(Wq, Wk, Wv, Wo, ff1, ff2, w16);
    init_kernel<<<(M_ * HID_ + 255) / 256, 256>>>(dn, attn);
    cvt16_kernel<<<(M_ * HID_ / 4) / 256, 256>>>(h, h16, nullptr);

    // 1. fused QKV projection -> fp16 QKV
    dim3 gq(HID3 / TBN, M_ / TBM);             // (3, 512)
    gemm_h<3><<<gq, 256, GEMM_SMEM_BYTES>>>(h16, w16 + W16_QKV, nullptr, QKV16, HID_, HID3);

    // 2. fused edge pass: logits + exp + denom + unnormalized scatter (4 edges/warp)
    edge_attn_kernel<<<(B_ * E_) / 32, 256>>>(QKV16, ef, eidx, nE, We, dn, attn);

    // 3. normalize attn by denom, convert to fp16
    cvt16_kernel<<<(M_ * HID_ / 4) / 256, 256>>>(attn, attn16, dn);

    // 4. output projection (+bo), residual + LN1 (fp32 + fp16 out)
    dim3 g1(1, M_ / TBM);
    gemm_h<1><<<g1, 256, GEMM_SMEM_BYTES>>>(attn16, w16 + W16_WO, bo, proj, HID_, HID_);
    add_ln_kernel<<<M_ / 8, 256>>>(proj, h, ln1g, ln1b, hmid, hmid16);

    // 5. FFN (ff1 -> fp16 intermediate, ff2 consumes fp16 A)
    dim3 g2(2, M_ / TBM);
    gemm_h<2><<<g2, 256, GEMM_SMEM_BYTES>>>(hmid16, w16 + W16_FF1, b1, ffb, HID_, 2 * HID_);
    gemm_h<1><<<g1, 256, GEMM_SMEM_BYTES>>>(ffb, w16 + W16_FF2, b2, proj, 2 * HID_, HID_);

    // 6. residual + LN2 -> output
    add_ln_kernel<<<M_ / 8, 256>>>(proj, hmid, ln2g, ln2b, out, nullptr);
}

// round 11
// speedup vs baseline: 1.0682x; 1.0682x over previous
#include <cuda_runtime.h>
#include <cuda_fp16.h>
#include <cstddef>
#include <cstdint>

// Problem constants
#define B_   4
#define N_   16384
#define E_   131072
#define HID_ 128
#define H_   8
#define D_   16
#define M_   (B_ * N_)   // 65536 flattened rows
#define HID3 384

// ---------------------------------------------------------------------------
// Scratch (device globals; no allocations allowed)
// ---------------------------------------------------------------------------
__device__ __half g_h16[(size_t)M_ * HID_];          // h in fp16 (QKV A)
__device__ __half g_QKV16[(size_t)M_ * HID3];        // Q|K|V packed per row, fp16
__device__ float  g_denom[(size_t)B_ * N_ * H_];
__device__ float  g_attn[(size_t)M_ * HID_];         // unnormalized Σ p·V
__device__ __half g_attn16[(size_t)M_ * HID_];       // normalized attn, fp16
__device__ float  g_proj[(size_t)M_ * HID_];         // Wo out, later ff2 out
__device__ float  g_hmid[(size_t)M_ * HID_];
__device__ __half g_hmid16[(size_t)M_ * HID_];       // LN1 out, fp16 (ff1 A)
__device__ __half g_ff16[(size_t)M_ * 2 * HID_];     // ff1 output (fp16)
__device__ __half g_w16[49152 + 16384 + 32768 + 32768]; // packed fp16 weights

#define W16_QKV 0
#define W16_WO  49152
#define W16_FF1 65536
#define W16_FF2 98304

// ---------------------------------------------------------------------------
// Helpers
// ---------------------------------------------------------------------------
__device__ __forceinline__ void cp_async16(uint32_t s, const void* g) {
    asm volatile("cp.async.cg.shared.global [%0], [%1], 16;" :: "r"(s), "l"(g));
}

__device__ __forceinline__ void ldsm_x4(uint32_t* r, uint32_t addr) {
    asm volatile("ldmatrix.sync.aligned.m8n8.x4.shared.b16 {%0,%1,%2,%3}, [%4];"
                 : "=r"(r[0]), "=r"(r[1]), "=r"(r[2]), "=r"(r[3]) : "r"(addr));
}
__device__ __forceinline__ void ldsm_x4_t(uint32_t* r, uint32_t addr) {
    asm volatile("ldmatrix.sync.aligned.m8n8.x4.trans.shared.b16 {%0,%1,%2,%3}, [%4];"
                 : "=r"(r[0]), "=r"(r[1]), "=r"(r[2]), "=r"(r[3]) : "r"(addr));
}
__device__ __forceinline__ void mma_f16(float* d, const uint32_t* a, uint32_t b0, uint32_t b1) {
    asm volatile(
        "mma.sync.aligned.m16n8k16.row.col.f32.f16.f16.f32 "
        "{%0,%1,%2,%3}, {%4,%5,%6,%7}, {%8,%9}, {%0,%1,%2,%3};"
        : "+f"(d[0]), "+f"(d[1]), "+f"(d[2]), "+f"(d[3])
        : "r"(a[0]), "r"(a[1]), "r"(a[2]), "r"(a[3]), "r"(b0), "r"(b1));
}

// dot of 4 fp16 pairs (as uint2) in fp32
__device__ __forceinline__ float dot4h(uint2 qa, uint2 ka) {
    float2 q0 = __half22float2(*(__half2*)&qa.x);
    float2 q1 = __half22float2(*(__half2*)&qa.y);
    float2 k0 = __half22float2(*(__half2*)&ka.x);
    float2 k1 = __half22float2(*(__half2*)&ka.y);
    return q0.x * k0.x + q0.y * k0.y + q1.x * k1.x + q1.y * k1.y;
}

// ---------------------------------------------------------------------------
// Weight pack: fp32 -> fp16. Wqkv interleaved [128][384], rest linear.
// ---------------------------------------------------------------------------
__global__ void prep_w16_kernel(const float* __restrict__ Wq, const float* __restrict__ Wk,
                                const float* __restrict__ Wv, const float* __restrict__ Wo,
                                const float* __restrict__ ff1, const float* __restrict__ ff2,
                                __half* __restrict__ w16) {
    int idx = blockIdx.x * blockDim.x + threadIdx.x;
    if (idx < 49152) {
        int k = idx / HID3, j = idx % HID3;
        float v = (j < 128) ? Wq[k * 128 + j]
                : (j < 256) ? Wk[k * 128 + j - 128]
                            : Wv[k * 128 + j - 256];
        w16[W16_QKV + idx] = __float2half(v);
    } else if (idx < 49152 + 16384) {
        w16[idx] = __float2half(Wo[idx - 49152]);
    } else if (idx < 49152 + 16384 + 32768) {
        w16[idx] = __float2half(ff1[idx - 65536]);
    } else {
        w16[idx] = __float2half(ff2[idx - 98304]);
    }
}

// ---------------------------------------------------------------------------
// Prologue: h -> fp16, attn = 0, denom = 0 (one fused pass)
// ---------------------------------------------------------------------------
__global__ void __launch_bounds__(256)
prologue_kernel(const float* __restrict__ h, __half* __restrict__ h16,
                float* __restrict__ attn, float* __restrict__ denom) {
    const size_t i = (size_t)blockIdx.x * blockDim.x + threadIdx.x; // M_*HID_/4
    const size_t off = i * 4;
    float4 v = *(const float4*)(h + off);
    uint2 o;
    *(__half2*)&o.x = __floats2half2_rn(v.x, v.y);
    *(__half2*)&o.y = __floats2half2_rn(v.z, v.w);
    *(uint2*)(h16 + off) = o;
    float4 z = {0.f, 0.f, 0.f, 0.f};
    *(float4*)(attn + off) = z;
    if (i < (size_t)B_ * N_ * H_) denom[i] = 0.0f;
}

// ---------------------------------------------------------------------------
// f32 -> f16 convert; divide by max(denom[row, col/16], 1e-6) (attn norm).
// ---------------------------------------------------------------------------
__global__ void __launch_bounds__(256)
cvt16_kernel(const float* __restrict__ in, __half* __restrict__ out,
             const float* __restrict__ dnm) {
    const size_t i = (size_t)blockIdx.x * blockDim.x + threadIdx.x; // M_*HID_/4
    const int row = (int)(i >> 5);
    const int c = ((int)i & 31) * 4;
    float4 v = *(const float4*)(in + (size_t)row * HID_ + c);
    const float dv = dnm[(size_t)row * H_ + (c >> 4)];
    const float inv = 1.0f / fmaxf(dv, 1e-6f);
    v.x *= inv; v.y *= inv; v.z *= inv; v.w *= inv;
    uint2 o;
    *(__half2*)&o.x = __floats2half2_rn(v.x, v.y);
    *(__half2*)&o.y = __floats2half2_rn(v.z, v.w);
    *(uint2*)(out + (size_t)row * HID_ + c) = o;
}

// ---------------------------------------------------------------------------
// FP16 tensor-core GEMM: C[M, Nn] = A16[M, Kk] @ B16[Kk, Nn]
// CTA tile 128x64 (3 CTAs/SM for latency hiding), TBK=64 double-buffered
// cp.async pipeline, 8 warps (4M x 2N), warp tile 32x32, mma.m16n8k16.
// EPI: 1 = +bias (f32 out), 2 = +bias+relu (f16 out), 3 = none (f16 out)
// ---------------------------------------------------------------------------
#define TBM 128
#define TBN 64
#define TBK 64
#define AST 72                          // halves per smem row (144B stride)
#define A_H (TBM * AST)                 // 9216 halves
#define B_H (TBK * AST)                 // 4608 halves
#define BUF_H (A_H + B_H)               // 13824 halves
#define GEMM_SMEM_BYTES (2 * BUF_H * 2) // 55296 B

template <int EPI>
__global__ void __launch_bounds__(256, 3)
gemm_h(const __half* __restrict__ Ap, const __half* __restrict__ Bp,
       const float* __restrict__ bias, void* __restrict__ Cp,
       int Kk, int Nn) {
    extern __shared__ __half sm[];

    const int tid  = threadIdx.x;
    const int wid  = tid >> 5;
    const int lane = tid & 31;
    const int g = lane >> 2;      // 0..7
    const int q = lane & 3;       // 0..3
    const int warpM = wid & 3;    // rows: 32 each
    const int warpN = wid >> 2;   // cols: 32 each
    const int rowBase = blockIdx.y * TBM;
    const int colBase = blockIdx.x * TBN;

    const uint32_t smem_u32 = (uint32_t)__cvta_generic_to_shared(sm);

    float acc[2][4][4];
    #pragma unroll
    for (int mt = 0; mt < 2; mt++)
        #pragma unroll
        for (int nt = 0; nt < 4; nt++)
            #pragma unroll
            for (int i = 0; i < 4; i++) acc[mt][nt][i] = 0.0f;

    const int lrow = lane & 15;
    const int lcol = (lane >> 4) * 8;
    const int nch = Kk / TBK;

    auto prefetch = [&](int buf, int k0) {
        const uint32_t base = smem_u32 + (uint32_t)buf * (BUF_H * 2);
        // A chunk: 128 rows x 64 halves = 1024 x 16B
        #pragma unroll
        for (int i = 0; i < 4; i++) {
            int idx = tid + i * 256;
            int r   = idx >> 3;
            int c8  = (idx & 7) * 8;
            cp_async16(base + (uint32_t)(r * AST + c8) * 2,
                       Ap + (size_t)(rowBase + r) * Kk + k0 + c8);
        }
        // B chunk: 64 rows x 64 halves = 512 x 16B
        const uint32_t bbase = base + A_H * 2;
        #pragma unroll
        for (int i = 0; i < 2; i++) {
            int idx = tid + i * 256;
            int r   = idx >> 3;
            int c8  = (idx & 7) * 8;
            cp_async16(bbase + (uint32_t)(r * AST + c8) * 2,
                       Bp + (size_t)(k0 + r) * Nn + colBase + c8);
        }
        asm volatile("cp.async.commit_group;");
    };

    prefetch(0, 0);

    for (int kc = 0; kc < nch; kc++) {
        if (kc + 1 < nch) {
            prefetch((kc + 1) & 1, (kc + 1) * TBK);
            asm volatile("cp.async.wait_group 1;");
        } else {
            asm volatile("cp.async.wait_group 0;");
        }
        __syncthreads();

        const uint32_t sbuf = smem_u32 + (uint32_t)(kc & 1) * (BUF_H * 2);
        const uint32_t sA = sbuf;
        const uint32_t sB = sbuf + A_H * 2;

        #pragma unroll
        for (int kk = 0; kk < 4; kk++) {
            uint32_t af[2][4];
            #pragma unroll
            for (int mt = 0; mt < 2; mt++)
                ldsm_x4(af[mt], sA + (uint32_t)((warpM * 32 + mt * 16 + lrow) * AST
                                                + kk * 16 + lcol) * 2);
            uint32_t bf[2][4];
            #pragma unroll
            for (int n4 = 0; n4 < 2; n4++)
                ldsm_x4_t(bf[n4], sB + (uint32_t)((kk * 16 + lrow) * AST
                                                  + warpN * 32 + n4 * 16 + lcol) * 2);
            #pragma unroll
            for (int mt = 0; mt < 2; mt++)
                #pragma unroll
                for (int nt = 0; nt < 4; nt++) {
                    const int n4 = nt >> 1, sel = (nt & 1) * 2;
                    mma_f16(acc[mt][nt], af[mt], bf[n4][sel], bf[n4][sel + 1]);
                }
        }
        __syncthreads();
    }

    // ---- epilogue ----
    #pragma unroll
    for (int mt = 0; mt < 2; mt++) {
        #pragma unroll
        for (int half = 0; half < 2; half++) {
            const int r = rowBase + warpM * 32 + mt * 16 + half * 8 + g;
            #pragma unroll
            for (int nt = 0; nt < 4; nt++) {
                const int c = colBase + warpN * 32 + nt * 8 + q * 2;
                float v0 = acc[mt][nt][half * 2 + 0];
                float v1 = acc[mt][nt][half * 2 + 1];
                if (EPI == 1 || EPI == 2) { v0 += bias[c]; v1 += bias[c + 1]; }
                if (EPI == 2) { v0 = fmaxf(v0, 0.0f); v1 = fmaxf(v1, 0.0f); }
                if (EPI >= 2) {
                    *(__half2*)((__half*)Cp + (size_t)r * Nn + c) = __floats2half2_rn(v0, v1);
                } else {
                    float2 o = {v0, v1};
                    *(float2*)((float*)Cp + (size_t)r * Nn + c) = o;
                }
            }
        }
    }
}

// ---------------------------------------------------------------------------
// Fused edge pass: logits -> p = exp -> denom += p, attn[dst] += p * V[src].
// FOUR edges per warp; lane -> head = lane/4, dv = lane%4. QKV fp16 packed
// per row: Q +0, K +128, V +256 (halves, stride HID3). No max pass;
// normalization deferred to the attn->fp16 convert pass.
// ---------------------------------------------------------------------------
__global__ void __launch_bounds__(256)
edge_attn_kernel(const __half* __restrict__ QKV,
                 const float* __restrict__ ef, const int* __restrict__ eidx,
                 const int* __restrict__ nE, const float* __restrict__ We,
                 float* __restrict__ denom, float* __restrict__ attn) {
    const int w = (blockIdx.x * blockDim.x + threadIdx.x) >> 5;
    const int lane = threadIdx.x & 31;
    const int b = w >> 15;              // E_/4 = 32768 warps per batch
    const int e0 = (w & 32767) * 4;
    const int ne = nE[b];
    if (e0 >= ne) return;
    const int cnt = min(4, ne - e0);

    const int head = lane >> 2;
    const int dv = lane & 3;
    const int hoff = head * D_ + dv * 4;

    const size_t ebase = (size_t)b * 2 * E_;
    const int4 srcs = *(const int4*)(eidx + ebase + e0);        // src e0..e0+3
    const int4 dsts = *(const int4*)(eidx + ebase + E_ + e0);   // dst e0..e0+3
    const int src[4] = {srcs.x, srcs.y, srcs.z, srcs.w};
    const int dst[4] = {dsts.x, dsts.y, dsts.z, dsts.w};

    // issue all gathers up-front (indices past cnt are still valid node ids)
    uint2 qv[4], kv[4], vv[4];
    #pragma unroll
    for (int i = 0; i < 4; i++) {
        const __half* qp = QKV + ((size_t)(b * N_ + dst[i])) * HID3 + hoff;
        const __half* kp = QKV + ((size_t)(b * N_ + src[i])) * HID3 + 128 + hoff;
        qv[i] = *(const uint2*)qp;
        kv[i] = *(const uint2*)kp;
        vv[i] = *(const uint2*)(kp + 128);
    }
    const float4 ef01 = *(const float4*)(ef + ((size_t)b * E_ + e0) * 2);
    const float4 ef23 = *(const float4*)(ef + ((size_t)b * E_ + e0) * 2 + 4);
    const float we0 = __ldg(We + head);
    const float we1 = __ldg(We + H_ + head);
    const float efe[4][2] = {{ef01.x, ef01.y}, {ef01.z, ef01.w},
                             {ef23.x, ef23.y}, {ef23.z, ef23.w}};

    float s[4];
    #pragma unroll
    for (int i = 0; i < 4; i++) s[i] = dot4h(qv[i], kv[i]);
    #pragma unroll
    for (int i = 0; i < 4; i++) {
        s[i] += __shfl_xor_sync(0xFFFFFFFFu, s[i], 1);
        s[i] += __shfl_xor_sync(0xFFFFFFFFu, s[i], 2);
    }

    #pragma unroll
    for (int i = 0; i < 4; i++) {
        if (i >= cnt) break;
        const float p = __expf(s[i] * 0.25f + efe[i][0] * we0 + efe[i][1] * we1);
        if (dv == 0)
            atomicAdd(denom + ((size_t)(b * N_ + dst[i])) * H_ + head, p);
        float2 a = __half22float2(*(__half2*)&vv[i].x);
        float2 c = __half22float2(*(__half2*)&vv[i].y);
        float* out = attn + ((size_t)(b * N_ + dst[i])) * HID_ + hoff;
        asm volatile("red.global.add.v4.f32 [%0], {%1, %2, %3, %4};"
                     :: "l"(out), "f"(p * a.x), "f"(p * a.y),
                        "f"(p * c.x), "f"(p * c.y) : "memory");
    }
}

// ---------------------------------------------------------------------------
// out = LayerNorm(x + res) * g + b (warp per 128-elem row).
// Optionally also writes fp16 copy (for the next GEMM's A operand).
// ---------------------------------------------------------------------------
__global__ void __launch_bounds__(256)
add_ln_kernel(const float* __restrict__ x, const float* __restrict__ res,
              const float* __restrict__ g, const float* __restrict__ bb,
              float* __restrict__ out, __half* __restrict__ out16) {
    const int row = (blockIdx.x * blockDim.x + threadIdx.x) >> 5;
    const int lane = threadIdx.x & 31;
    const size_t off = (size_t)row * HID_ + lane * 4;

    const float4 a = *(const float4*)(x + off);
    const float4 r = *(const float4*)(res + off);
    float4 v = {a.x + r.x, a.y + r.y, a.z + r.z, a.w + r.w};

    float sum = v.x + v.y + v.z + v.w;
    float sq  = v.x * v.x + v.y * v.y + v.z * v.z + v.w * v.w;
    #pragma unroll
    for (int s = 16; s; s >>= 1) {
        sum += __shfl_xor_sync(0xFFFFFFFFu, sum, s);
        sq  += __shfl_xor_sync(0xFFFFFFFFu, sq, s);
    }
    const float mean = sum * (1.0f / 128.0f);
    const float var  = sq * (1.0f / 128.0f) - mean * mean;
    const float rs   = rsqrtf(var + 1e-5f);

    const float4 gg = *(const float4*)(g + lane * 4);
    const float4 bv = *(const float4*)(bb + lane * 4);
    float4 o;
    o.x = (v.x - mean) * rs * gg.x + bv.x;
    o.y = (v.y - mean) * rs * gg.y + bv.y;
    o.z = (v.z - mean) * rs * gg.z + bv.z;
    o.w = (v.w - mean) * rs * gg.w + bv.w;
    *(float4*)(out + off) = o;
    if (out16) {
        uint2 hh;
        *(__half2*)&hh.x = __floats2half2_rn(o.x, o.y);
        *(__half2*)&hh.y = __floats2half2_rn(o.z, o.w);
        *(uint2*)(out16 + off) = hh;
    }
}

// ---------------------------------------------------------------------------
// Launch
// ---------------------------------------------------------------------------
extern "C" void kernel_launch(void* const* d_in, const int* in_sizes, int n_in,
                              void* d_out, int out_size) {
    const float* h    = (const float*)d_in[0];
    const float* ef   = (const float*)d_in[1];
    const int*   eidx = (const int*)d_in[2];
    const int*   nE   = (const int*)d_in[3];
    const float* Wq   = (const float*)d_in[4];
    const float* Wk   = (const float*)d_in[5];
    const float* Wv   = (const float*)d_in[6];
    const float* Wo   = (const float*)d_in[7];
    const float* bo   = (const float*)d_in[8];
    const float* We   = (const float*)d_in[9];
    const float* ln1g = (const float*)d_in[10];
    const float* ln1b = (const float*)d_in[11];
    const float* ln2g = (const float*)d_in[12];
    const float* ln2b = (const float*)d_in[13];
    const float* ff1  = (const float*)d_in[14];
    const float* b1   = (const float*)d_in[15];
    const float* ff2  = (const float*)d_in[16];
    const float* b2   = (const float*)d_in[17];
    float* out = (float*)d_out;

    float *dn, *attn, *proj, *hmid;
    __half *h16, *QKV16, *attn16, *hmid16, *ffb, *w16;
    cudaGetSymbolAddress((void**)&h16, g_h16);
    cudaGetSymbolAddress((void**)&QKV16, g_QKV16);
    cudaGetSymbolAddress((void**)&dn, g_denom);
    cudaGetSymbolAddress((void**)&attn, g_attn);
    cudaGetSymbolAddress((void**)&attn16, g_attn16);
    cudaGetSymbolAddress((void**)&proj, g_proj);
    cudaGetSymbolAddress((void**)&hmid, g_hmid);
    cudaGetSymbolAddress((void**)&hmid16, g_hmid16);
    cudaGetSymbolAddress((void**)&ffb, g_ff16);
    cudaGetSymbolAddress((void**)&w16, g_w16);

    static bool attr_done = false;
    if (!attr_done) {
        cudaFuncSetAttribute((const void*)gemm_h<1>, cudaFuncAttributeMaxDynamicSharedMemorySize, GEMM_SMEM_BYTES);
        cudaFuncSetAttribute((const void*)gemm_h<2>, cudaFuncAttributeMaxDynamicSharedMemorySize, GEMM_SMEM_BYTES);
        cudaFuncSetAttribute((const void*)gemm_h<3>, cudaFuncAttributeMaxDynamicSharedMemorySize, GEMM_SMEM_BYTES);
        attr_done = true;
    }

    // 0. weight pack (fp32 -> fp16); fused prologue (h->fp16, attn=0, denom=0)
    prep_w16_kernel<<<512, 256>>>(Wq, Wk, Wv, Wo, ff1, ff2, w16);
    prologue_kernel<<<(M_ * HID_ / 4) / 256, 256>>>(h, h16, attn, dn);

    // 1. fused QKV projection -> fp16 QKV
    dim3 gq(HID3 / TBN, M_ / TBM);             // (6, 512)
    gemm_h<3><<<gq, 256, GEMM_SMEM_BYTES>>>(h16, w16 + W16_QKV, nullptr, QKV16, HID_, HID3);

    // 2. fused edge pass: logits + exp + denom + unnormalized scatter (4 edges/warp)
    edge_attn_kernel<<<(B_ * E_) / 32, 256>>>(QKV16, ef, eidx, nE, We, dn, attn);

    // 3. normalize attn by denom, convert to fp16
    cvt16_kernel<<<(M_ * HID_ / 4) / 256, 256>>>(attn, attn16, dn);

    // 4. output projection (+bo), residual + LN1 (fp32 + fp16 out)
    dim3 g1(HID_ / TBN, M_ / TBM);             // (2, 512)
    gemm_h<1><<<g1, 256, GEMM_SMEM_BYTES>>>(attn16, w16 + W16_WO, bo, proj, HID_, HID_);
    add_ln_kernel<<<M_ / 8, 256>>>(proj, h, ln1g, ln1b, hmid, hmid16);

    // 5. FFN (ff1 -> fp16 intermediate, ff2 consumes fp16 A)
    dim3 g2(2 * HID_ / TBN, M_ / TBM);         // (4, 512)
    gemm_h<2><<<g2, 256, GEMM_SMEM_BYTES>>>(hmid16, w16 + W16_FF1, b1, ffb, HID_, 2 * HID_);
    gemm_h<1><<<g1, 256, GEMM_SMEM_BYTES>>>(ffb, w16 + W16_FF2, b2, proj, 2 * HID_, HID_);

    // 6. residual + LN2 -> output
    add_ln_kernel<<<M_ / 8, 256>>>(proj, hmid, ln2g, ln2b, out, nullptr);
}

// round 12
// speedup vs baseline: 1.1139x; 1.0429x over previous
#include <cuda_runtime.h>
#include <cuda_fp16.h>
#include <cstddef>
#include <cstdint>

// Problem constants
#define B_   4
#define N_   16384
#define E_   131072
#define HID_ 128
#define H_   8
#define D_   16
#define M_   (B_ * N_)   // 65536 flattened rows
#define HID3 384

// ---------------------------------------------------------------------------
// Scratch (device globals; no allocations allowed)
// ---------------------------------------------------------------------------
__device__ __half g_h16[(size_t)M_ * HID_];          // h in fp16 (QKV A)
__device__ __half g_QKV16[(size_t)M_ * HID3];        // Q|K|V packed per row, fp16
__device__ float  g_denom[(size_t)B_ * N_ * H_];
__device__ float  g_attn[(size_t)M_ * HID_];         // unnormalized Σ p·V
__device__ __half g_attn16[(size_t)M_ * HID_];       // normalized attn, fp16
__device__ float  g_hmid[(size_t)M_ * HID_];         // LN1 out (fp32)
__device__ __half g_hmid16[(size_t)M_ * HID_];       // LN1 out, fp16 (ff1 A)
__device__ __half g_ff16[(size_t)M_ * 2 * HID_];     // ff1 output (fp16)
__device__ __half g_w16[49152 + 16384 + 32768 + 32768]; // packed fp16 weights

#define W16_QKV 0
#define W16_WO  49152
#define W16_FF1 65536
#define W16_FF2 98304

// ---------------------------------------------------------------------------
// Helpers
// ---------------------------------------------------------------------------
__device__ __forceinline__ void cp_async16(uint32_t s, const void* g) {
    asm volatile("cp.async.cg.shared.global [%0], [%1], 16;" :: "r"(s), "l"(g));
}

__device__ __forceinline__ void ldsm_x4(uint32_t* r, uint32_t addr) {
    asm volatile("ldmatrix.sync.aligned.m8n8.x4.shared.b16 {%0,%1,%2,%3}, [%4];"
                 : "=r"(r[0]), "=r"(r[1]), "=r"(r[2]), "=r"(r[3]) : "r"(addr));
}
__device__ __forceinline__ void ldsm_x4_t(uint32_t* r, uint32_t addr) {
    asm volatile("ldmatrix.sync.aligned.m8n8.x4.trans.shared.b16 {%0,%1,%2,%3}, [%4];"
                 : "=r"(r[0]), "=r"(r[1]), "=r"(r[2]), "=r"(r[3]) : "r"(addr));
}
__device__ __forceinline__ void mma_f16(float* d, const uint32_t* a, uint32_t b0, uint32_t b1) {
    asm volatile(
        "mma.sync.aligned.m16n8k16.row.col.f32.f16.f16.f32 "
        "{%0,%1,%2,%3}, {%4,%5,%6,%7}, {%8,%9}, {%0,%1,%2,%3};"
        : "+f"(d[0]), "+f"(d[1]), "+f"(d[2]), "+f"(d[3])
        : "r"(a[0]), "r"(a[1]), "r"(a[2]), "r"(a[3]), "r"(b0), "r"(b1));
}

// dot of 4 fp16 pairs (as uint2) in fp32
__device__ __forceinline__ float dot4h(uint2 qa, uint2 ka) {
    float2 q0 = __half22float2(*(__half2*)&qa.x);
    float2 q1 = __half22float2(*(__half2*)&qa.y);
    float2 k0 = __half22float2(*(__half2*)&ka.x);
    float2 k1 = __half22float2(*(__half2*)&ka.y);
    return q0.x * k0.x + q0.y * k0.y + q1.x * k1.x + q1.y * k1.y;
}

// ---------------------------------------------------------------------------
// Weight pack: fp32 -> fp16. Wqkv interleaved [128][384], rest linear.
// ---------------------------------------------------------------------------
__global__ void prep_w16_kernel(const float* __restrict__ Wq, const float* __restrict__ Wk,
                                const float* __restrict__ Wv, const float* __restrict__ Wo,
                                const float* __restrict__ ff1, const float* __restrict__ ff2,
                                __half* __restrict__ w16) {
    int idx = blockIdx.x * blockDim.x + threadIdx.x;
    if (idx < 49152) {
        int k = idx / HID3, j = idx % HID3;
        float v = (j < 128) ? Wq[k * 128 + j]
                : (j < 256) ? Wk[k * 128 + j - 128]
                            : Wv[k * 128 + j - 256];
        w16[W16_QKV + idx] = __float2half(v);
    } else if (idx < 49152 + 16384) {
        w16[idx] = __float2half(Wo[idx - 49152]);
    } else if (idx < 49152 + 16384 + 32768) {
        w16[idx] = __float2half(ff1[idx - 65536]);
    } else {
        w16[idx] = __float2half(ff2[idx - 98304]);
    }
}

// ---------------------------------------------------------------------------
// Prologue: h -> fp16, attn = 0, denom = 0 (one fused pass)
// ---------------------------------------------------------------------------
__global__ void __launch_bounds__(256)
prologue_kernel(const float* __restrict__ h, __half* __restrict__ h16,
                float* __restrict__ attn, float* __restrict__ denom) {
    const size_t i = (size_t)blockIdx.x * blockDim.x + threadIdx.x; // M_*HID_/4
    const size_t off = i * 4;
    float4 v = *(const float4*)(h + off);
    uint2 o;
    *(__half2*)&o.x = __floats2half2_rn(v.x, v.y);
    *(__half2*)&o.y = __floats2half2_rn(v.z, v.w);
    *(uint2*)(h16 + off) = o;
    float4 z = {0.f, 0.f, 0.f, 0.f};
    *(float4*)(attn + off) = z;
    if (i < (size_t)B_ * N_ * H_) denom[i] = 0.0f;
}

// ---------------------------------------------------------------------------
// f32 -> f16 convert; divide by max(denom[row, col/16], 1e-6) (attn norm).
// ---------------------------------------------------------------------------
__global__ void __launch_bounds__(256)
cvt16_kernel(const float* __restrict__ in, __half* __restrict__ out,
             const float* __restrict__ dnm) {
    const size_t i = (size_t)blockIdx.x * blockDim.x + threadIdx.x; // M_*HID_/4
    const int row = (int)(i >> 5);
    const int c = ((int)i & 31) * 4;
    float4 v = *(const float4*)(in + (size_t)row * HID_ + c);
    const float dv = dnm[(size_t)row * H_ + (c >> 4)];
    const float inv = 1.0f / fmaxf(dv, 1e-6f);
    v.x *= inv; v.y *= inv; v.z *= inv; v.w *= inv;
    uint2 o;
    *(__half2*)&o.x = __floats2half2_rn(v.x, v.y);
    *(__half2*)&o.y = __floats2half2_rn(v.z, v.w);
    *(uint2*)(out + (size_t)row * HID_ + c) = o;
}

// ===========================================================================
// GEMM kernel 1: wide-N, occ-3 (for QKV and ff1)
// CTA tile 128x64, TBK=64 double-buffered cp.async, 8 warps (4M x 2N),
// warp tile 32x32, mma.m16n8k16.  EPI: 2 = +bias+relu (f16), 3 = none (f16)
// ===========================================================================
#define TBM 128
#define TBN 64
#define TBK 64
#define AST 72                          // halves per smem row (144B stride)
#define A_H (TBM * AST)                 // 9216 halves
#define B_H (TBK * AST)                 // 4608 halves
#define BUF_H (A_H + B_H)               // 13824 halves
#define GEMM_SMEM_BYTES (2 * BUF_H * 2) // 55296 B

template <int EPI>
__global__ void __launch_bounds__(256, 3)
gemm_h(const __half* __restrict__ Ap, const __half* __restrict__ Bp,
       const float* __restrict__ bias, __half* __restrict__ Cp,
       int Kk, int Nn) {
    extern __shared__ __half sm[];

    const int tid  = threadIdx.x;
    const int wid  = tid >> 5;
    const int lane = tid & 31;
    const int g = lane >> 2;
    const int q = lane & 3;
    const int warpM = wid & 3;
    const int warpN = wid >> 2;
    const int rowBase = blockIdx.y * TBM;
    const int colBase = blockIdx.x * TBN;

    const uint32_t smem_u32 = (uint32_t)__cvta_generic_to_shared(sm);

    float acc[2][4][4];
    #pragma unroll
    for (int mt = 0; mt < 2; mt++)
        #pragma unroll
        for (int nt = 0; nt < 4; nt++)
            #pragma unroll
            for (int i = 0; i < 4; i++) acc[mt][nt][i] = 0.0f;

    const int lrow = lane & 15;
    const int lcol = (lane >> 4) * 8;
    const int nch = Kk / TBK;

    auto prefetch = [&](int buf, int k0) {
        const uint32_t base = smem_u32 + (uint32_t)buf * (BUF_H * 2);
        #pragma unroll
        for (int i = 0; i < 4; i++) {
            int idx = tid + i * 256;
            int r   = idx >> 3;
            int c8  = (idx & 7) * 8;
            cp_async16(base + (uint32_t)(r * AST + c8) * 2,
                       Ap + (size_t)(rowBase + r) * Kk + k0 + c8);
        }
        const uint32_t bbase = base + A_H * 2;
        #pragma unroll
        for (int i = 0; i < 2; i++) {
            int idx = tid + i * 256;
            int r   = idx >> 3;
            int c8  = (idx & 7) * 8;
            cp_async16(bbase + (uint32_t)(r * AST + c8) * 2,
                       Bp + (size_t)(k0 + r) * Nn + colBase + c8);
        }
        asm volatile("cp.async.commit_group;");
    };

    prefetch(0, 0);

    for (int kc = 0; kc < nch; kc++) {
        if (kc + 1 < nch) {
            prefetch((kc + 1) & 1, (kc + 1) * TBK);
            asm volatile("cp.async.wait_group 1;");
        } else {
            asm volatile("cp.async.wait_group 0;");
        }
        __syncthreads();

        const uint32_t sbuf = smem_u32 + (uint32_t)(kc & 1) * (BUF_H * 2);
        const uint32_t sA = sbuf;
        const uint32_t sB = sbuf + A_H * 2;

        #pragma unroll
        for (int kk = 0; kk < 4; kk++) {
            uint32_t af[2][4];
            #pragma unroll
            for (int mt = 0; mt < 2; mt++)
                ldsm_x4(af[mt], sA + (uint32_t)((warpM * 32 + mt * 16 + lrow) * AST
                                                + kk * 16 + lcol) * 2);
            uint32_t bf[2][4];
            #pragma unroll
            for (int n4 = 0; n4 < 2; n4++)
                ldsm_x4_t(bf[n4], sB + (uint32_t)((kk * 16 + lrow) * AST
                                                  + warpN * 32 + n4 * 16 + lcol) * 2);
            #pragma unroll
            for (int mt = 0; mt < 2; mt++)
                #pragma unroll
                for (int nt = 0; nt < 4; nt++) {
                    const int n4 = nt >> 1, sel = (nt & 1) * 2;
                    mma_f16(acc[mt][nt], af[mt], bf[n4][sel], bf[n4][sel + 1]);
                }
        }
        __syncthreads();
    }

    #pragma unroll
    for (int mt = 0; mt < 2; mt++) {
        #pragma unroll
        for (int half = 0; half < 2; half++) {
            const int r = rowBase + warpM * 32 + mt * 16 + half * 8 + g;
            #pragma unroll
            for (int nt = 0; nt < 4; nt++) {
                const int c = colBase + warpN * 32 + nt * 8 + q * 2;
                float v0 = acc[mt][nt][half * 2 + 0];
                float v1 = acc[mt][nt][half * 2 + 1];
                if (EPI == 2) {
                    v0 = fmaxf(v0 + bias[c], 0.0f);
                    v1 = fmaxf(v1 + bias[c + 1], 0.0f);
                }
                *(__half2*)(Cp + (size_t)r * Nn + c) = __floats2half2_rn(v0, v1);
            }
        }
    }
}

// ===========================================================================
// GEMM kernel 2: full-row TBN=128 with fused bias + residual + LayerNorm.
// CTA tile 128x128 (Nn == 128), 8 warps (4M x 2N), warp tile 32x64.
// Epilogue: v = acc + bias + res; row mean/var via quad-shfl + smem combine;
// writes fp32 out and optional fp16 out.
// ===========================================================================
#define LAST 72
#define LBST 136
#define LA_H (TBM * LAST)                // 9216
#define LB_H (TBK * LBST)                // 9792? no: 64*136 = 8704
#define LBUF_H (LA_H + 8704)             // 17920
#define GEMMLN_SMEM_BYTES (2 * LBUF_H * 2)  // 71680

template <bool HALF_OUT>
__global__ void __launch_bounds__(256, 2)
gemm_ln(const __half* __restrict__ Ap, const __half* __restrict__ Bp,
        const float* __restrict__ bias, const float* __restrict__ res,
        const float* __restrict__ lng, const float* __restrict__ lnb,
        float* __restrict__ outf, __half* __restrict__ outh, int Kk) {
    extern __shared__ __half sm[];
    const int Nn = HID_;

    const int tid  = threadIdx.x;
    const int wid  = tid >> 5;
    const int lane = tid & 31;
    const int g = lane >> 2;
    const int q = lane & 3;
    const int warpM = wid & 3;    // rows: 32 each
    const int warpN = wid >> 2;   // cols: 64 each
    const int rowBase = blockIdx.y * TBM;

    const uint32_t smem_u32 = (uint32_t)__cvta_generic_to_shared(sm);

    float acc[2][8][4];
    #pragma unroll
    for (int mt = 0; mt < 2; mt++)
        #pragma unroll
        for (int nt = 0; nt < 8; nt++)
            #pragma unroll
            for (int i = 0; i < 4; i++) acc[mt][nt][i] = 0.0f;

    const int lrow = lane & 15;
    const int lcol = (lane >> 4) * 8;
    const int nch = Kk / TBK;

    auto prefetch = [&](int buf, int k0) {
        const uint32_t base = smem_u32 + (uint32_t)buf * (LBUF_H * 2);
        #pragma unroll
        for (int i = 0; i < 4; i++) {           // A: 128r x 64h
            int idx = tid + i * 256;
            int r   = idx >> 3;
            int c8  = (idx & 7) * 8;
            cp_async16(base + (uint32_t)(r * LAST + c8) * 2,
                       Ap + (size_t)(rowBase + r) * Kk + k0 + c8);
        }
        const uint32_t bbase = base + LA_H * 2;
        #pragma unroll
        for (int i = 0; i < 4; i++) {           // B: 64r x 128h
            int idx = tid + i * 256;
            int r   = idx >> 4;
            int c8  = (idx & 15) * 8;
            cp_async16(bbase + (uint32_t)(r * LBST + c8) * 2,
                       Bp + (size_t)(k0 + r) * Nn + c8);
        }
        asm volatile("cp.async.commit_group;");
    };

    prefetch(0, 0);

    for (int kc = 0; kc < nch; kc++) {
        if (kc + 1 < nch) {
            prefetch((kc + 1) & 1, (kc + 1) * TBK);
            asm volatile("cp.async.wait_group 1;");
        } else {
            asm volatile("cp.async.wait_group 0;");
        }
        __syncthreads();

        const uint32_t sbuf = smem_u32 + (uint32_t)(kc & 1) * (LBUF_H * 2);
        const uint32_t sA = sbuf;
        const uint32_t sB = sbuf + LA_H * 2;

        #pragma unroll
        for (int kk = 0; kk < 4; kk++) {
            uint32_t af[2][4];
            #pragma unroll
            for (int mt = 0; mt < 2; mt++)
                ldsm_x4(af[mt], sA + (uint32_t)((warpM * 32 + mt * 16 + lrow) * LAST
                                                + kk * 16 + lcol) * 2);
            uint32_t bf[4][4];
            #pragma unroll
            for (int n4 = 0; n4 < 4; n4++)
                ldsm_x4_t(bf[n4], sB + (uint32_t)((kk * 16 + lrow) * LBST
                                                  + warpN * 64 + n4 * 16 + lcol) * 2);
            #pragma unroll
            for (int mt = 0; mt < 2; mt++)
                #pragma unroll
                for (int nt = 0; nt < 8; nt++) {
                    const int n4 = nt >> 1, sel = (nt & 1) * 2;
                    mma_f16(acc[mt][nt], af[mt], bf[n4][sel], bf[n4][sel + 1]);
                }
        }
        __syncthreads();
    }

    // ---- LN epilogue ----
    // reuse smem for row-stat exchange: [warpM][mt][half][g][warpN] x {sum,sq}
    float* red = (float*)sm;
    __syncthreads();   // all compute done; safe to overwrite smem

    // pass 1: v = acc + bias + res (in-place into acc), per-row partial sums
    #pragma unroll
    for (int mt = 0; mt < 2; mt++) {
        #pragma unroll
        for (int half = 0; half < 2; half++) {
            const int r = rowBase + warpM * 32 + mt * 16 + half * 8 + g;
            float s1 = 0.0f, s2 = 0.0f;
            #pragma unroll
            for (int nt = 0; nt < 8; nt++) {
                const int c = warpN * 64 + nt * 8 + q * 2;
                const float2 rr = *(const float2*)(res + (size_t)r * Nn + c);
                float v0 = acc[mt][nt][half * 2 + 0] + bias[c]     + rr.x;
                float v1 = acc[mt][nt][half * 2 + 1] + bias[c + 1] + rr.y;
                acc[mt][nt][half * 2 + 0] = v0;
                acc[mt][nt][half * 2 + 1] = v1;
                s1 += v0 + v1;
                s2 += v0 * v0 + v1 * v1;
            }
            s1 += __shfl_xor_sync(0xFFFFFFFFu, s1, 1);
            s1 += __shfl_xor_sync(0xFFFFFFFFu, s1, 2);
            s2 += __shfl_xor_sync(0xFFFFFFFFu, s2, 1);
            s2 += __shfl_xor_sync(0xFFFFFFFFu, s2, 2);
            if (q == 0) {
                const int idx = ((((warpM * 2 + mt) * 2 + half) * 8 + g) * 2 + warpN);
                red[idx * 2 + 0] = s1;
                red[idx * 2 + 1] = s2;
            }
        }
    }
    __syncthreads();

    // pass 2: combine the two warpN halves, normalize, store
    #pragma unroll
    for (int mt = 0; mt < 2; mt++) {
        #pragma unroll
        for (int half = 0; half < 2; half++) {
            const int r = rowBase + warpM * 32 + mt * 16 + half * 8 + g;
            const int ibase = ((((warpM * 2 + mt) * 2 + half) * 8 + g) * 2);
            const float sum = red[ibase * 2 + 0] + red[(ibase + 1) * 2 + 0];
            const float sq  = red[ibase * 2 + 1] + red[(ibase + 1) * 2 + 1];
            const float mean = sum * (1.0f / 128.0f);
            const float var  = sq * (1.0f / 128.0f) - mean * mean;
            const float rs   = rsqrtf(var + 1e-5f);
            #pragma unroll
            for (int nt = 0; nt < 8; nt++) {
                const int c = warpN * 64 + nt * 8 + q * 2;
                const float o0 = (acc[mt][nt][half * 2 + 0] - mean) * rs * lng[c]     + lnb[c];
                const float o1 = (acc[mt][nt][half * 2 + 1] - mean) * rs * lng[c + 1] + lnb[c + 1];
                float2 of = {o0, o1};
                *(float2*)(outf + (size_t)r * Nn + c) = of;
                if (HALF_OUT)
                    *(__half2*)(outh + (size_t)r * Nn + c) = __floats2half2_rn(o0, o1);
            }
        }
    }
}

// ---------------------------------------------------------------------------
// Fused edge pass: logits -> p = exp -> denom += p, attn[dst] += p * V[src].
// FOUR edges per warp; lane -> head = lane/4, dv = lane%4. QKV fp16 packed
// per row: Q +0, K +128, V +256 (halves, stride HID3). No max pass;
// normalization deferred to the attn->fp16 convert pass.
// ---------------------------------------------------------------------------
__global__ void __launch_bounds__(256)
edge_attn_kernel(const __half* __restrict__ QKV,
                 const float* __restrict__ ef, const int* __restrict__ eidx,
                 const int* __restrict__ nE, const float* __restrict__ We,
                 float* __restrict__ denom, float* __restrict__ attn) {
    const int w = (blockIdx.x * blockDim.x + threadIdx.x) >> 5;
    const int lane = threadIdx.x & 31;
    const int b = w >> 15;              // E_/4 = 32768 warps per batch
    const int e0 = (w & 32767) * 4;
    const int ne = nE[b];
    if (e0 >= ne) return;
    const int cnt = min(4, ne - e0);

    const int head = lane >> 2;
    const int dv = lane & 3;
    const int hoff = head * D_ + dv * 4;

    const size_t ebase = (size_t)b * 2 * E_;
    const int4 srcs = *(const int4*)(eidx + ebase + e0);
    const int4 dsts = *(const int4*)(eidx + ebase + E_ + e0);
    const int src[4] = {srcs.x, srcs.y, srcs.z, srcs.w};
    const int dst[4] = {dsts.x, dsts.y, dsts.z, dsts.w};

    uint2 qv[4], kv[4], vv[4];
    #pragma unroll
    for (int i = 0; i < 4; i++) {
        const __half* qp = QKV + ((size_t)(b * N_ + dst[i])) * HID3 + hoff;
        const __half* kp = QKV + ((size_t)(b * N_ + src[i])) * HID3 + 128 + hoff;
        qv[i] = *(const uint2*)qp;
        kv[i] = *(const uint2*)kp;
        vv[i] = *(const uint2*)(kp + 128);
    }
    const float4 ef01 = *(const float4*)(ef + ((size_t)b * E_ + e0) * 2);
    const float4 ef23 = *(const float4*)(ef + ((size_t)b * E_ + e0) * 2 + 4);
    const float we0 = __ldg(We + head);
    const float we1 = __ldg(We + H_ + head);
    const float efe[4][2] = {{ef01.x, ef01.y}, {ef01.z, ef01.w},
                             {ef23.x, ef23.y}, {ef23.z, ef23.w}};

    float s[4];
    #pragma unroll
    for (int i = 0; i < 4; i++) s[i] = dot4h(qv[i], kv[i]);
    #pragma unroll
    for (int i = 0; i < 4; i++) {
        s[i] += __shfl_xor_sync(0xFFFFFFFFu, s[i], 1);
        s[i] += __shfl_xor_sync(0xFFFFFFFFu, s[i], 2);
    }

    #pragma unroll
    for (int i = 0; i < 4; i++) {
        if (i >= cnt) break;
        const float p = __expf(s[i] * 0.25f + efe[i][0] * we0 + efe[i][1] * we1);
        if (dv == 0)
            atomicAdd(denom + ((size_t)(b * N_ + dst[i])) * H_ + head, p);
        float2 a = __half22float2(*(__half2*)&vv[i].x);
        float2 c = __half22float2(*(__half2*)&vv[i].y);
        float* out = attn + ((size_t)(b * N_ + dst[i])) * HID_ + hoff;
        asm volatile("red.global.add.v4.f32 [%0], {%1, %2, %3, %4};"
                     :: "l"(out), "f"(p * a.x), "f"(p * a.y),
                        "f"(p * c.x), "f"(p * c.y) : "memory");
    }
}

// ---------------------------------------------------------------------------
// Launch
// ---------------------------------------------------------------------------
extern "C" void kernel_launch(void* const* d_in, const int* in_sizes, int n_in,
                              void* d_out, int out_size) {
    const float* h    = (const float*)d_in[0];
    const float* ef   = (const float*)d_in[1];
    const int*   eidx = (const int*)d_in[2];
    const int*   nE   = (const int*)d_in[3];
    const float* Wq   = (const float*)d_in[4];
    const float* Wk   = (const float*)d_in[5];
    const float* Wv   = (const float*)d_in[6];
    const float* Wo   = (const float*)d_in[7];
    const float* bo   = (const float*)d_in[8];
    const float* We   = (const float*)d_in[9];
    const float* ln1g = (const float*)d_in[10];
    const float* ln1b = (const float*)d_in[11];
    const float* ln2g = (const float*)d_in[12];
    const float* ln2b = (const float*)d_in[13];
    const float* ff1  = (const float*)d_in[14];
    const float* b1   = (const float*)d_in[15];
    const float* ff2  = (const float*)d_in[16];
    const float* b2   = (const float*)d_in[17];
    float* out = (float*)d_out;

    float *dn, *attn, *hmid;
    __half *h16, *QKV16, *attn16, *hmid16, *ffb, *w16;
    cudaGetSymbolAddress((void**)&h16, g_h16);
    cudaGetSymbolAddress((void**)&QKV16, g_QKV16);
    cudaGetSymbolAddress((void**)&dn, g_denom);
    cudaGetSymbolAddress((void**)&attn, g_attn);
    cudaGetSymbolAddress((void**)&attn16, g_attn16);
    cudaGetSymbolAddress((void**)&hmid, g_hmid);
    cudaGetSymbolAddress((void**)&hmid16, g_hmid16);
    cudaGetSymbolAddress((void**)&ffb, g_ff16);
    cudaGetSymbolAddress((void**)&w16, g_w16);

    static bool attr_done = false;
    if (!attr_done) {
        cudaFuncSetAttribute((const void*)gemm_h<2>, cudaFuncAttributeMaxDynamicSharedMemorySize, GEMM_SMEM_BYTES);
        cudaFuncSetAttribute((const void*)gemm_h<3>, cudaFuncAttributeMaxDynamicSharedMemorySize, GEMM_SMEM_BYTES);
        cudaFuncSetAttribute((const void*)gemm_ln<true>,  cudaFuncAttributeMaxDynamicSharedMemorySize, GEMMLN_SMEM_BYTES);
        cudaFuncSetAttribute((const void*)gemm_ln<false>, cudaFuncAttributeMaxDynamicSharedMemorySize, GEMMLN_SMEM_BYTES);
        attr_done = true;
    }

    // 0. weight pack; fused prologue (h->fp16, attn=0, denom=0)
    prep_w16_kernel<<<512, 256>>>(Wq, Wk, Wv, Wo, ff1, ff2, w16);
    prologue_kernel<<<(M_ * HID_ / 4) / 256, 256>>>(h, h16, attn, dn);

    // 1. fused QKV projection -> fp16 QKV
    dim3 gq(HID3 / TBN, M_ / TBM);             // (6, 512)
    gemm_h<3><<<gq, 256, GEMM_SMEM_BYTES>>>(h16, w16 + W16_QKV, nullptr, QKV16, HID_, HID3);

    // 2. fused edge pass: logits + exp + denom + unnormalized scatter
    edge_attn_kernel<<<(B_ * E_) / 32, 256>>>(QKV16, ef, eidx, nE, We, dn, attn);

    // 3. normalize attn by denom, convert to fp16
    cvt16_kernel<<<(M_ * HID_ / 4) / 256, 256>>>(attn, attn16, dn);

    // 4. Wo GEMM + bias + residual(h) + LN1 fused -> hmid (f32) + hmid16 (f16)
    dim3 gl(1, M_ / TBM);
    gemm_ln<true><<<gl, 256, GEMMLN_SMEM_BYTES>>>(attn16, w16 + W16_WO, bo, h,
                                                  ln1g, ln1b, hmid, hmid16, HID_);

    // 5. ff1 (+bias+relu -> fp16)
    dim3 g2(2 * HID_ / TBN, M_ / TBM);         // (4, 512)
    gemm_h<2><<<g2, 256, GEMM_SMEM_BYTES>>>(hmid16, w16 + W16_FF1, b1, ffb, HID_, 2 * HID_);

    // 6. ff2 GEMM + bias + residual(hmid) + LN2 fused -> out
    gemm_ln<false><<<gl, 256, GEMMLN_SMEM_BYTES>>>(ffb, w16 + W16_FF2, b2, hmid,
                                                   ln2g, ln2b, out, nullptr, 2 * HID_);
}

// round 13
// speedup vs baseline: 1.1488x; 1.0313x over previous
#include <cuda_runtime.h>
#include <cuda_fp16.h>
#include <cstddef>
#include <cstdint>

// Problem constants
#define B_   4
#define N_   16384
#define E_   131072
#define HID_ 128
#define H_   8
#define D_   16
#define M_   (B_ * N_)   // 65536 flattened rows
#define HID3 384

// ---------------------------------------------------------------------------
// Scratch (device globals; no allocations allowed)
// ---------------------------------------------------------------------------
__device__ __half g_h16[(size_t)M_ * HID_];          // QKV A; later normalized attn
__device__ __half g_QKV16[(size_t)M_ * HID3];        // Q|K|V packed per row, fp16
__device__ float  g_denom[(size_t)B_ * N_ * H_];
__device__ __half g_attn16[(size_t)M_ * HID_];       // fp16 Σ p·V (atomic target)
__device__ float  g_hmid[(size_t)M_ * HID_];         // LN1 out (fp32)
__device__ __half g_hmid16[(size_t)M_ * HID_];       // LN1 out, fp16 (ff1 A)
__device__ __half g_ff16[(size_t)M_ * 2 * HID_];     // ff1 output (fp16)
__device__ __half g_w16[49152 + 16384 + 32768 + 32768]; // packed fp16 weights

#define W16_QKV 0
#define W16_WO  49152
#define W16_FF1 65536
#define W16_FF2 98304

// ---------------------------------------------------------------------------
// Helpers
// ---------------------------------------------------------------------------
__device__ __forceinline__ void cp_async16(uint32_t s, const void* g) {
    asm volatile("cp.async.cg.shared.global [%0], [%1], 16;" :: "r"(s), "l"(g));
}

__device__ __forceinline__ void ldsm_x4(uint32_t* r, uint32_t addr) {
    asm volatile("ldmatrix.sync.aligned.m8n8.x4.shared.b16 {%0,%1,%2,%3}, [%4];"
                 : "=r"(r[0]), "=r"(r[1]), "=r"(r[2]), "=r"(r[3]) : "r"(addr));
}
__device__ __forceinline__ void ldsm_x4_t(uint32_t* r, uint32_t addr) {
    asm volatile("ldmatrix.sync.aligned.m8n8.x4.trans.shared.b16 {%0,%1,%2,%3}, [%4];"
                 : "=r"(r[0]), "=r"(r[1]), "=r"(r[2]), "=r"(r[3]) : "r"(addr));
}
__device__ __forceinline__ void mma_f16(float* d, const uint32_t* a, uint32_t b0, uint32_t b1) {
    asm volatile(
        "mma.sync.aligned.m16n8k16.row.col.f32.f16.f16.f32 "
        "{%0,%1,%2,%3}, {%4,%5,%6,%7}, {%8,%9}, {%0,%1,%2,%3};"
        : "+f"(d[0]), "+f"(d[1]), "+f"(d[2]), "+f"(d[3])
        : "r"(a[0]), "r"(a[1]), "r"(a[2]), "r"(a[3]), "r"(b0), "r"(b1));
}

// dot of 4 fp16 pairs (as uint2) in fp32
__device__ __forceinline__ float dot4h(uint2 qa, uint2 ka) {
    float2 q0 = __half22float2(*(__half2*)&qa.x);
    float2 q1 = __half22float2(*(__half2*)&qa.y);
    float2 k0 = __half22float2(*(__half2*)&ka.x);
    float2 k1 = __half22float2(*(__half2*)&ka.y);
    return q0.x * k0.x + q0.y * k0.y + q1.x * k1.x + q1.y * k1.y;
}

// ---------------------------------------------------------------------------
// Weight pack: fp32 -> fp16. Wqkv interleaved [128][384], rest linear.
// ---------------------------------------------------------------------------
__global__ void prep_w16_kernel(const float* __restrict__ Wq, const float* __restrict__ Wk,
                                const float* __restrict__ Wv, const float* __restrict__ Wo,
                                const float* __restrict__ ff1, const float* __restrict__ ff2,
                                __half* __restrict__ w16) {
    int idx = blockIdx.x * blockDim.x + threadIdx.x;
    if (idx < 49152) {
        int k = idx / HID3, j = idx % HID3;
        float v = (j < 128) ? Wq[k * 128 + j]
                : (j < 256) ? Wk[k * 128 + j - 128]
                            : Wv[k * 128 + j - 256];
        w16[W16_QKV + idx] = __float2half(v);
    } else if (idx < 49152 + 16384) {
        w16[idx] = __float2half(Wo[idx - 49152]);
    } else if (idx < 49152 + 16384 + 32768) {
        w16[idx] = __float2half(ff1[idx - 65536]);
    } else {
        w16[idx] = __float2half(ff2[idx - 98304]);
    }
}

// ---------------------------------------------------------------------------
// Prologue: h -> fp16 (into h16), attn16 = 0, denom = 0 (one fused pass)
// ---------------------------------------------------------------------------
__global__ void __launch_bounds__(256)
prologue_kernel(const float* __restrict__ h, __half* __restrict__ h16,
                __half* __restrict__ attn16, float* __restrict__ denom) {
    const size_t i = (size_t)blockIdx.x * blockDim.x + threadIdx.x; // M_*HID_/4
    const size_t off = i * 4;
    float4 v = *(const float4*)(h + off);
    uint2 o;
    *(__half2*)&o.x = __floats2half2_rn(v.x, v.y);
    *(__half2*)&o.y = __floats2half2_rn(v.z, v.w);
    *(uint2*)(h16 + off) = o;
    uint2 z = {0u, 0u};
    *(uint2*)(attn16 + off) = z;
    if (i < (size_t)B_ * N_ * H_) denom[i] = 0.0f;
}

// ---------------------------------------------------------------------------
// Normalize: attn16 /= max(denom[row, col/16], 1e-6) -> out16 (fp16)
// ---------------------------------------------------------------------------
__global__ void __launch_bounds__(256)
norm16_kernel(const __half* __restrict__ in, __half* __restrict__ out,
              const float* __restrict__ dnm) {
    const size_t i = (size_t)blockIdx.x * blockDim.x + threadIdx.x; // M_*HID_/4
    const int row = (int)(i >> 5);
    const int c = ((int)i & 31) * 4;
    uint2 raw = *(const uint2*)(in + (size_t)row * HID_ + c);
    float2 v0 = __half22float2(*(__half2*)&raw.x);
    float2 v1 = __half22float2(*(__half2*)&raw.y);
    const float dv = dnm[(size_t)row * H_ + (c >> 4)];
    const float inv = 1.0f / fmaxf(dv, 1e-6f);
    uint2 o;
    *(__half2*)&o.x = __floats2half2_rn(v0.x * inv, v0.y * inv);
    *(__half2*)&o.y = __floats2half2_rn(v1.x * inv, v1.y * inv);
    *(uint2*)(out + (size_t)row * HID_ + c) = o;
}

// ===========================================================================
// GEMM kernel 1: wide-N, occ-3 (for QKV and ff1)
// CTA tile 128x64, TBK=64 double-buffered cp.async, 8 warps (4M x 2N),
// warp tile 32x32, mma.m16n8k16.  EPI: 2 = +bias+relu (f16), 3 = none (f16)
// ===========================================================================
#define TBM 128
#define TBN 64
#define TBK 64
#define AST 72                          // halves per smem row (144B stride)
#define A_H (TBM * AST)                 // 9216 halves
#define B_H (TBK * AST)                 // 4608 halves
#define BUF_H (A_H + B_H)               // 13824 halves
#define GEMM_SMEM_BYTES (2 * BUF_H * 2) // 55296 B

template <int EPI>
__global__ void __launch_bounds__(256, 3)
gemm_h(const __half* __restrict__ Ap, const __half* __restrict__ Bp,
       const float* __restrict__ bias, __half* __restrict__ Cp,
       int Kk, int Nn) {
    extern __shared__ __half sm[];

    const int tid  = threadIdx.x;
    const int wid  = tid >> 5;
    const int lane = tid & 31;
    const int g = lane >> 2;
    const int q = lane & 3;
    const int warpM = wid & 3;
    const int warpN = wid >> 2;
    const int rowBase = blockIdx.y * TBM;
    const int colBase = blockIdx.x * TBN;

    const uint32_t smem_u32 = (uint32_t)__cvta_generic_to_shared(sm);

    float acc[2][4][4];
    #pragma unroll
    for (int mt = 0; mt < 2; mt++)
        #pragma unroll
        for (int nt = 0; nt < 4; nt++)
            #pragma unroll
            for (int i = 0; i < 4; i++) acc[mt][nt][i] = 0.0f;

    const int lrow = lane & 15;
    const int lcol = (lane >> 4) * 8;
    const int nch = Kk / TBK;

    auto prefetch = [&](int buf, int k0) {
        const uint32_t base = smem_u32 + (uint32_t)buf * (BUF_H * 2);
        #pragma unroll
        for (int i = 0; i < 4; i++) {
            int idx = tid + i * 256;
            int r   = idx >> 3;
            int c8  = (idx & 7) * 8;
            cp_async16(base + (uint32_t)(r * AST + c8) * 2,
                       Ap + (size_t)(rowBase + r) * Kk + k0 + c8);
        }
        const uint32_t bbase = base + A_H * 2;
        #pragma unroll
        for (int i = 0; i < 2; i++) {
            int idx = tid + i * 256;
            int r   = idx >> 3;
            int c8  = (idx & 7) * 8;
            cp_async16(bbase + (uint32_t)(r * AST + c8) * 2,
                       Bp + (size_t)(k0 + r) * Nn + colBase + c8);
        }
        asm volatile("cp.async.commit_group;");
    };

    prefetch(0, 0);

    for (int kc = 0; kc < nch; kc++) {
        if (kc + 1 < nch) {
            prefetch((kc + 1) & 1, (kc + 1) * TBK);
            asm volatile("cp.async.wait_group 1;");
        } else {
            asm volatile("cp.async.wait_group 0;");
        }
        __syncthreads();

        const uint32_t sbuf = smem_u32 + (uint32_t)(kc & 1) * (BUF_H * 2);
        const uint32_t sA = sbuf;
        const uint32_t sB = sbuf + A_H * 2;

        #pragma unroll
        for (int kk = 0; kk < 4; kk++) {
            uint32_t af[2][4];
            #pragma unroll
            for (int mt = 0; mt < 2; mt++)
                ldsm_x4(af[mt], sA + (uint32_t)((warpM * 32 + mt * 16 + lrow) * AST
                                                + kk * 16 + lcol) * 2);
            uint32_t bf[2][4];
            #pragma unroll
            for (int n4 = 0; n4 < 2; n4++)
                ldsm_x4_t(bf[n4], sB + (uint32_t)((kk * 16 + lrow) * AST
                                                  + warpN * 32 + n4 * 16 + lcol) * 2);
            #pragma unroll
            for (int mt = 0; mt < 2; mt++)
                #pragma unroll
                for (int nt = 0; nt < 4; nt++) {
                    const int n4 = nt >> 1, sel = (nt & 1) * 2;
                    mma_f16(acc[mt][nt], af[mt], bf[n4][sel], bf[n4][sel + 1]);
                }
        }
        __syncthreads();
    }

    #pragma unroll
    for (int mt = 0; mt < 2; mt++) {
        #pragma unroll
        for (int half = 0; half < 2; half++) {
            const int r = rowBase + warpM * 32 + mt * 16 + half * 8 + g;
            #pragma unroll
            for (int nt = 0; nt < 4; nt++) {
                const int c = colBase + warpN * 32 + nt * 8 + q * 2;
                float v0 = acc[mt][nt][half * 2 + 0];
                float v1 = acc[mt][nt][half * 2 + 1];
                if (EPI == 2) {
                    v0 = fmaxf(v0 + bias[c], 0.0f);
                    v1 = fmaxf(v1 + bias[c + 1], 0.0f);
                }
                *(__half2*)(Cp + (size_t)r * Nn + c) = __floats2half2_rn(v0, v1);
            }
        }
    }
}

// ===========================================================================
// GEMM kernel 2: full-row TBN=128 with fused bias + residual + LayerNorm.
// CTA tile 128x128 (Nn == 128), 8 warps (4M x 2N), warp tile 32x64.
// ===========================================================================
#define LAST 72
#define LBST 136
#define LA_H (TBM * LAST)                // 9216
#define LBUF_H (LA_H + 8704)             // 17920
#define GEMMLN_SMEM_BYTES (2 * LBUF_H * 2)  // 71680

template <bool HALF_OUT>
__global__ void __launch_bounds__(256, 2)
gemm_ln(const __half* __restrict__ Ap, const __half* __restrict__ Bp,
        const float* __restrict__ bias, const float* __restrict__ res,
        const float* __restrict__ lng, const float* __restrict__ lnb,
        float* __restrict__ outf, __half* __restrict__ outh, int Kk) {
    extern __shared__ __half sm[];
    const int Nn = HID_;

    const int tid  = threadIdx.x;
    const int wid  = tid >> 5;
    const int lane = tid & 31;
    const int g = lane >> 2;
    const int q = lane & 3;
    const int warpM = wid & 3;
    const int warpN = wid >> 2;
    const int rowBase = blockIdx.y * TBM;

    const uint32_t smem_u32 = (uint32_t)__cvta_generic_to_shared(sm);

    float acc[2][8][4];
    #pragma unroll
    for (int mt = 0; mt < 2; mt++)
        #pragma unroll
        for (int nt = 0; nt < 8; nt++)
            #pragma unroll
            for (int i = 0; i < 4; i++) acc[mt][nt][i] = 0.0f;

    const int lrow = lane & 15;
    const int lcol = (lane >> 4) * 8;
    const int nch = Kk / TBK;

    auto prefetch = [&](int buf, int k0) {
        const uint32_t base = smem_u32 + (uint32_t)buf * (LBUF_H * 2);
        #pragma unroll
        for (int i = 0; i < 4; i++) {           // A: 128r x 64h
            int idx = tid + i * 256;
            int r   = idx >> 3;
            int c8  = (idx & 7) * 8;
            cp_async16(base + (uint32_t)(r * LAST + c8) * 2,
                       Ap + (size_t)(rowBase + r) * Kk + k0 + c8);
        }
        const uint32_t bbase = base + LA_H * 2;
        #pragma unroll
        for (int i = 0; i < 4; i++) {           // B: 64r x 128h
            int idx = tid + i * 256;
            int r   = idx >> 4;
            int c8  = (idx & 15) * 8;
            cp_async16(bbase + (uint32_t)(r * LBST + c8) * 2,
                       Bp + (size_t)(k0 + r) * Nn + c8);
        }
        asm volatile("cp.async.commit_group;");
    };

    prefetch(0, 0);

    for (int kc = 0; kc < nch; kc++) {
        if (kc + 1 < nch) {
            prefetch((kc + 1) & 1, (kc + 1) * TBK);
            asm volatile("cp.async.wait_group 1;");
        } else {
            asm volatile("cp.async.wait_group 0;");
        }
        __syncthreads();

        const uint32_t sbuf = smem_u32 + (uint32_t)(kc & 1) * (LBUF_H * 2);
        const uint32_t sA = sbuf;
        const uint32_t sB = sbuf + LA_H * 2;

        #pragma unroll
        for (int kk = 0; kk < 4; kk++) {
            uint32_t af[2][4];
            #pragma unroll
            for (int mt = 0; mt < 2; mt++)
                ldsm_x4(af[mt], sA + (uint32_t)((warpM * 32 + mt * 16 + lrow) * LAST
                                                + kk * 16 + lcol) * 2);
            uint32_t bf[4][4];
            #pragma unroll
            for (int n4 = 0; n4 < 4; n4++)
                ldsm_x4_t(bf[n4], sB + (uint32_t)((kk * 16 + lrow) * LBST
                                                  + warpN * 64 + n4 * 16 + lcol) * 2);
            #pragma unroll
            for (int mt = 0; mt < 2; mt++)
                #pragma unroll
                for (int nt = 0; nt < 8; nt++) {
                    const int n4 = nt >> 1, sel = (nt & 1) * 2;
                    mma_f16(acc[mt][nt], af[mt], bf[n4][sel], bf[n4][sel + 1]);
                }
        }
        __syncthreads();
    }

    // ---- LN epilogue ----
    float* red = (float*)sm;
    __syncthreads();

    #pragma unroll
    for (int mt = 0; mt < 2; mt++) {
        #pragma unroll
        for (int half = 0; half < 2; half++) {
            const int r = rowBase + warpM * 32 + mt * 16 + half * 8 + g;
            float s1 = 0.0f, s2 = 0.0f;
            #pragma unroll
            for (int nt = 0; nt < 8; nt++) {
                const int c = warpN * 64 + nt * 8 + q * 2;
                const float2 rr = *(const float2*)(res + (size_t)r * Nn + c);
                float v0 = acc[mt][nt][half * 2 + 0] + bias[c]     + rr.x;
                float v1 = acc[mt][nt][half * 2 + 1] + bias[c + 1] + rr.y;
                acc[mt][nt][half * 2 + 0] = v0;
                acc[mt][nt][half * 2 + 1] = v1;
                s1 += v0 + v1;
                s2 += v0 * v0 + v1 * v1;
            }
            s1 += __shfl_xor_sync(0xFFFFFFFFu, s1, 1);
            s1 += __shfl_xor_sync(0xFFFFFFFFu, s1, 2);
            s2 += __shfl_xor_sync(0xFFFFFFFFu, s2, 1);
            s2 += __shfl_xor_sync(0xFFFFFFFFu, s2, 2);
            if (q == 0) {
                const int idx = ((((warpM * 2 + mt) * 2 + half) * 8 + g) * 2 + warpN);
                red[idx * 2 + 0] = s1;
                red[idx * 2 + 1] = s2;
            }
        }
    }
    __syncthreads();

    #pragma unroll
    for (int mt = 0; mt < 2; mt++) {
        #pragma unroll
        for (int half = 0; half < 2; half++) {
            const int r = rowBase + warpM * 32 + mt * 16 + half * 8 + g;
            const int ibase = ((((warpM * 2 + mt) * 2 + half) * 8 + g) * 2);
            const float sum = red[ibase * 2 + 0] + red[(ibase + 1) * 2 + 0];
            const float sq  = red[ibase * 2 + 1] + red[(ibase + 1) * 2 + 1];
            const float mean = sum * (1.0f / 128.0f);
            const float var  = sq * (1.0f / 128.0f) - mean * mean;
            const float rs   = rsqrtf(var + 1e-5f);
            #pragma unroll
            for (int nt = 0; nt < 8; nt++) {
                const int c = warpN * 64 + nt * 8 + q * 2;
                const float o0 = (acc[mt][nt][half * 2 + 0] - mean) * rs * lng[c]     + lnb[c];
                const float o1 = (acc[mt][nt][half * 2 + 1] - mean) * rs * lng[c + 1] + lnb[c + 1];
                float2 of = {o0, o1};
                *(float2*)(outf + (size_t)r * Nn + c) = of;
                if (HALF_OUT)
                    *(__half2*)(outh + (size_t)r * Nn + c) = __floats2half2_rn(o0, o1);
            }
        }
    }
}

// ---------------------------------------------------------------------------
// Fused edge pass: logits -> p = exp -> denom += p, attn16[dst] += p * V[src]
// (fp16 atomics, halves the scatter traffic). FOUR edges per warp; lane ->
// head = lane/4, dv = lane%4. QKV fp16 packed per row: Q +0, K +128, V +256.
// ---------------------------------------------------------------------------
__global__ void __launch_bounds__(256)
edge_attn_kernel(const __half* __restrict__ QKV,
                 const float* __restrict__ ef, const int* __restrict__ eidx,
                 const int* __restrict__ nE, const float* __restrict__ We,
                 float* __restrict__ denom, __half* __restrict__ attn16) {
    const int w = (blockIdx.x * blockDim.x + threadIdx.x) >> 5;
    const int lane = threadIdx.x & 31;
    const int b = w >> 15;              // E_/4 = 32768 warps per batch
    const int e0 = (w & 32767) * 4;
    const int ne = nE[b];
    if (e0 >= ne) return;
    const int cnt = min(4, ne - e0);

    const int head = lane >> 2;
    const int dv = lane & 3;
    const int hoff = head * D_ + dv * 4;

    const size_t ebase = (size_t)b * 2 * E_;
    const int4 srcs = *(const int4*)(eidx + ebase + e0);
    const int4 dsts = *(const int4*)(eidx + ebase + E_ + e0);
    const int src[4] = {srcs.x, srcs.y, srcs.z, srcs.w};
    const int dst[4] = {dsts.x, dsts.y, dsts.z, dsts.w};

    uint2 qv[4], kv[4], vv[4];
    #pragma unroll
    for (int i = 0; i < 4; i++) {
        const __half* qp = QKV + ((size_t)(b * N_ + dst[i])) * HID3 + hoff;
        const __half* kp = QKV + ((size_t)(b * N_ + src[i])) * HID3 + 128 + hoff;
        qv[i] = *(const uint2*)qp;
        kv[i] = *(const uint2*)kp;
        vv[i] = *(const uint2*)(kp + 128);
    }
    const float4 ef01 = *(const float4*)(ef + ((size_t)b * E_ + e0) * 2);
    const float4 ef23 = *(const float4*)(ef + ((size_t)b * E_ + e0) * 2 + 4);
    const float we0 = __ldg(We + head);
    const float we1 = __ldg(We + H_ + head);
    const float efe[4][2] = {{ef01.x, ef01.y}, {ef01.z, ef01.w},
                             {ef23.x, ef23.y}, {ef23.z, ef23.w}};

    float s[4];
    #pragma unroll
    for (int i = 0; i < 4; i++) s[i] = dot4h(qv[i], kv[i]);
    #pragma unroll
    for (int i = 0; i < 4; i++) {
        s[i] += __shfl_xor_sync(0xFFFFFFFFu, s[i], 1);
        s[i] += __shfl_xor_sync(0xFFFFFFFFu, s[i], 2);
    }

    #pragma unroll
    for (int i = 0; i < 4; i++) {
        if (i >= cnt) break;
        const float p = __expf(s[i] * 0.25f + efe[i][0] * we0 + efe[i][1] * we1);
        if (dv == 0)
            atomicAdd(denom + ((size_t)(b * N_ + dst[i])) * H_ + head, p);
        float2 a = __half22float2(*(__half2*)&vv[i].x);
        float2 c = __half22float2(*(__half2*)&vv[i].y);
        uint32_t pv0, pv1;
        *(__half2*)&pv0 = __floats2half2_rn(p * a.x, p * a.y);
        *(__half2*)&pv1 = __floats2half2_rn(p * c.x, p * c.y);
        __half* out = attn16 + ((size_t)(b * N_ + dst[i])) * HID_ + hoff;
        asm volatile("red.global.add.noftz.f16x2 [%0], %1;"
                     :: "l"(out), "r"(pv0) : "memory");
        asm volatile("red.global.add.noftz.f16x2 [%0], %1;"
                     :: "l"(out + 2), "r"(pv1) : "memory");
    }
}

// ---------------------------------------------------------------------------
// Launch
// ---------------------------------------------------------------------------
extern "C" void kernel_launch(void* const* d_in, const int* in_sizes, int n_in,
                              void* d_out, int out_size) {
    const float* h    = (const float*)d_in[0];
    const float* ef   = (const float*)d_in[1];
    const int*   eidx = (const int*)d_in[2];
    const int*   nE   = (const int*)d_in[3];
    const float* Wq   = (const float*)d_in[4];
    const float* Wk   = (const float*)d_in[5];
    const float* Wv   = (const float*)d_in[6];
    const float* Wo   = (const float*)d_in[7];
    const float* bo   = (const float*)d_in[8];
    const float* We   = (const float*)d_in[9];
    const float* ln1g = (const float*)d_in[10];
    const float* ln1b = (const float*)d_in[11];
    const float* ln2g = (const float*)d_in[12];
    const float* ln2b = (const float*)d_in[13];
    const float* ff1  = (const float*)d_in[14];
    const float* b1   = (const float*)d_in[15];
    const float* ff2  = (const float*)d_in[16];
    const float* b2   = (const float*)d_in[17];
    float* out = (float*)d_out;

    float *dn, *hmid;
    __half *h16, *QKV16, *attn16, *hmid16, *ffb, *w16;
    cudaGetSymbolAddress((void**)&h16, g_h16);
    cudaGetSymbolAddress((void**)&QKV16, g_QKV16);
    cudaGetSymbolAddress((void**)&dn, g_denom);
    cudaGetSymbolAddress((void**)&attn16, g_attn16);
    cudaGetSymbolAddress((void**)&hmid, g_hmid);
    cudaGetSymbolAddress((void**)&hmid16, g_hmid16);
    cudaGetSymbolAddress((void**)&ffb, g_ff16);
    cudaGetSymbolAddress((void**)&w16, g_w16);

    static bool attr_done = false;
    if (!attr_done) {
        cudaFuncSetAttribute((const void*)gemm_h<2>, cudaFuncAttributeMaxDynamicSharedMemorySize, GEMM_SMEM_BYTES);
        cudaFuncSetAttribute((const void*)gemm_h<3>, cudaFuncAttributeMaxDynamicSharedMemorySize, GEMM_SMEM_BYTES);
        cudaFuncSetAttribute((const void*)gemm_ln<true>,  cudaFuncAttributeMaxDynamicSharedMemorySize, GEMMLN_SMEM_BYTES);
        cudaFuncSetAttribute((const void*)gemm_ln<false>, cudaFuncAttributeMaxDynamicSharedMemorySize, GEMMLN_SMEM_BYTES);
        attr_done = true;
    }

    // 0. weight pack; fused prologue (h->fp16, attn16=0, denom=0)
    prep_w16_kernel<<<512, 256>>>(Wq, Wk, Wv, Wo, ff1, ff2, w16);
    prologue_kernel<<<(M_ * HID_ / 4) / 256, 256>>>(h, h16, attn16, dn);

    // 1. fused QKV projection -> fp16 QKV
    dim3 gq(HID3 / TBN, M_ / TBM);             // (6, 512)
    gemm_h<3><<<gq, 256, GEMM_SMEM_BYTES>>>(h16, w16 + W16_QKV, nullptr, QKV16, HID_, HID3);

    // 2. fused edge pass: logits + exp + denom + fp16 scatter
    edge_attn_kernel<<<(B_ * E_) / 32, 256>>>(QKV16, ef, eidx, nE, We, dn, attn16);

    // 3. normalize attn16 by denom -> h16 (reused; dead after QKV GEMM)
    norm16_kernel<<<(M_ * HID_ / 4) / 256, 256>>>(attn16, h16, dn);

    // 4. Wo GEMM + bias + residual(h) + LN1 fused -> hmid (f32) + hmid16 (f16)
    dim3 gl(1, M_ / TBM);
    gemm_ln<true><<<gl, 256, GEMMLN_SMEM_BYTES>>>(h16, w16 + W16_WO, bo, h,
                                                  ln1g, ln1b, hmid, hmid16, HID_);

    // 5. ff1 (+bias+relu -> fp16)
    dim3 g2(2 * HID_ / TBN, M_ / TBM);         // (4, 512)
    gemm_h<2><<<g2, 256, GEMM_SMEM_BYTES>>>(hmid16, w16 + W16_FF1, b1, ffb, HID_, 2 * HID_);

    // 6. ff2 GEMM + bias + residual(hmid) + LN2 fused -> out
    gemm_ln<false><<<gl, 256, GEMMLN_SMEM_BYTES>>>(ffb, w16 + W16_FF2, b2, hmid,
                                                   ln2g, ln2b, out, nullptr, 2 * HID_);
}

// round 15
// speedup vs baseline: 1.2047x; 1.0487x over previous
#include <cuda_runtime.h>
#include <cuda_fp16.h>
#include <cstddef>
#include <cstdint>

// Problem constants
#define B_   4
#define N_   16384
#define E_   131072
#define HID_ 128
#define H_   8
#define D_   16
#define M_   (B_ * N_)   // 65536 flattened rows
#define HID3 384

// ---------------------------------------------------------------------------
// Scratch (device globals; no allocations allowed)
// ---------------------------------------------------------------------------
__device__ __half g_h16[(size_t)M_ * HID_];          // h in fp16 (QKV A)
__device__ __half g_QKV16[(size_t)M_ * HID3];        // Q|K|V packed per row, fp16
__device__ float  g_denom[(size_t)B_ * N_ * H_];
__device__ __half g_attn16[(size_t)M_ * HID_];       // fp16 Σ p·V (atomic target)
__device__ __half g_hmid16[(size_t)M_ * HID_];       // LN1 out, fp16
__device__ __half g_ff16[(size_t)M_ * 2 * HID_];     // ff1 output (fp16)
__device__ __half g_w16[49152 + 16384 + 32768 + 32768]; // packed fp16 weights

#define W16_QKV 0
#define W16_WO  49152
#define W16_FF1 65536
#define W16_FF2 98304

// ---------------------------------------------------------------------------
// Helpers
// ---------------------------------------------------------------------------
__device__ __forceinline__ void cp_async16(uint32_t s, const void* g) {
    asm volatile("cp.async.cg.shared.global [%0], [%1], 16;" :: "r"(s), "l"(g));
}

__device__ __forceinline__ void ldsm_x4(uint32_t* r, uint32_t addr) {
    asm volatile("ldmatrix.sync.aligned.m8n8.x4.shared.b16 {%0,%1,%2,%3}, [%4];"
                 : "=r"(r[0]), "=r"(r[1]), "=r"(r[2]), "=r"(r[3]) : "r"(addr));
}
__device__ __forceinline__ void ldsm_x4_t(uint32_t* r, uint32_t addr) {
    asm volatile("ldmatrix.sync.aligned.m8n8.x4.trans.shared.b16 {%0,%1,%2,%3}, [%4];"
                 : "=r"(r[0]), "=r"(r[1]), "=r"(r[2]), "=r"(r[3]) : "r"(addr));
}
__device__ __forceinline__ void mma_f16(float* d, const uint32_t* a, uint32_t b0, uint32_t b1) {
    asm volatile(
        "mma.sync.aligned.m16n8k16.row.col.f32.f16.f16.f32 "
        "{%0,%1,%2,%3}, {%4,%5,%6,%7}, {%8,%9}, {%0,%1,%2,%3};"
        : "+f"(d[0]), "+f"(d[1]), "+f"(d[2]), "+f"(d[3])
        : "r"(a[0]), "r"(a[1]), "r"(a[2]), "r"(a[3]), "r"(b0), "r"(b1));
}

// dot of 4 fp16 pairs (as uint2) in fp32
__device__ __forceinline__ float dot4h(uint2 qa, uint2 ka) {
    float2 q0 = __half22float2(*(__half2*)&qa.x);
    float2 q1 = __half22float2(*(__half2*)&qa.y);
    float2 k0 = __half22float2(*(__half2*)&ka.x);
    float2 k1 = __half22float2(*(__half2*)&ka.y);
    return q0.x * k0.x + q0.y * k0.y + q1.x * k1.x + q1.y * k1.y;
}

// ---------------------------------------------------------------------------
// Weight pack: fp32 -> fp16. Wqkv interleaved [128][384], rest linear.
// ---------------------------------------------------------------------------
__global__ void prep_w16_kernel(const float* __restrict__ Wq, const float* __restrict__ Wk,
                                const float* __restrict__ Wv, const float* __restrict__ Wo,
                                const float* __restrict__ ff1, const float* __restrict__ ff2,
                                __half* __restrict__ w16) {
    int idx = blockIdx.x * blockDim.x + threadIdx.x;
    if (idx < 49152) {
        int k = idx / HID3, j = idx % HID3;
        float v = (j < 128) ? Wq[k * 128 + j]
                : (j < 256) ? Wk[k * 128 + j - 128]
                            : Wv[k * 128 + j - 256];
        w16[W16_QKV + idx] = __float2half(v);
    } else if (idx < 49152 + 16384) {
        w16[idx] = __float2half(Wo[idx - 49152]);
    } else if (idx < 49152 + 16384 + 32768) {
        w16[idx] = __float2half(ff1[idx - 65536]);
    } else {
        w16[idx] = __float2half(ff2[idx - 98304]);
    }
}

// ---------------------------------------------------------------------------
// Prologue: h -> fp16 (into h16), attn16 = 0, denom = 0 (one fused pass)
// ---------------------------------------------------------------------------
__global__ void __launch_bounds__(256)
prologue_kernel(const float* __restrict__ h, __half* __restrict__ h16,
                __half* __restrict__ attn16, float* __restrict__ denom) {
    const size_t i = (size_t)blockIdx.x * blockDim.x + threadIdx.x; // M_*HID_/4
    const size_t off = i * 4;
    float4 v = *(const float4*)(h + off);
    uint2 o;
    *(__half2*)&o.x = __floats2half2_rn(v.x, v.y);
    *(__half2*)&o.y = __floats2half2_rn(v.z, v.w);
    *(uint2*)(h16 + off) = o;
    uint2 z = {0u, 0u};
    *(uint2*)(attn16 + off) = z;
    if (i < (size_t)B_ * N_ * H_) denom[i] = 0.0f;
}

// ===========================================================================
// GEMM kernel 1: wide-N, occ-3 (for QKV and ff1)
// CTA tile 128x64, TBK=64 double-buffered cp.async, 8 warps (4M x 2N),
// warp tile 32x32, mma.m16n8k16.  EPI: 2 = +bias+relu (f16), 3 = none (f16)
// ===========================================================================
#define TBM 128
#define TBN 64
#define TBK 64
#define AST 72                          // halves per smem row (144B stride)
#define A_H (TBM * AST)                 // 9216 halves
#define B_H (TBK * AST)                 // 4608 halves
#define BUF_H (A_H + B_H)               // 13824 halves
#define GEMM_SMEM_BYTES (2 * BUF_H * 2) // 55296 B

template <int EPI>
__global__ void __launch_bounds__(256, 3)
gemm_h(const __half* __restrict__ Ap, const __half* __restrict__ Bp,
       const float* __restrict__ bias, __half* __restrict__ Cp,
       int Kk, int Nn) {
    extern __shared__ __half sm[];

    const int tid  = threadIdx.x;
    const int wid  = tid >> 5;
    const int lane = tid & 31;
    const int g = lane >> 2;
    const int q = lane & 3;
    const int warpM = wid & 3;
    const int warpN = wid >> 2;
    const int rowBase = blockIdx.y * TBM;
    const int colBase = blockIdx.x * TBN;

    const uint32_t smem_u32 = (uint32_t)__cvta_generic_to_shared(sm);

    float acc[2][4][4];
    #pragma unroll
    for (int mt = 0; mt < 2; mt++)
        #pragma unroll
        for (int nt = 0; nt < 4; nt++)
            #pragma unroll
            for (int i = 0; i < 4; i++) acc[mt][nt][i] = 0.0f;

    const int lrow = lane & 15;
    const int lcol = (lane >> 4) * 8;
    const int nch = Kk / TBK;

    auto prefetch = [&](int buf, int k0) {
        const uint32_t base = smem_u32 + (uint32_t)buf * (BUF_H * 2);
        #pragma unroll
        for (int i = 0; i < 4; i++) {           // A: 128r x 64h = 1024 x 16B
            int idx = tid + i * 256;
            int r   = idx >> 3;
            int c8  = (idx & 7) * 8;
            cp_async16(base + (uint32_t)(r * AST + c8) * 2,
                       Ap + (size_t)(rowBase + r) * Kk + k0 + c8);
        }
        const uint32_t bbase = base + A_H * 2;
        #pragma unroll
        for (int i = 0; i < 2; i++) {           // B: 64r x 64h = 512 x 16B
            int idx = tid + i * 256;
            int r   = idx >> 3;
            int c8  = (idx & 7) * 8;
            cp_async16(bbase + (uint32_t)(r * AST + c8) * 2,
                       Bp + (size_t)(k0 + r) * Nn + colBase + c8);
        }
        asm volatile("cp.async.commit_group;");
    };

    prefetch(0, 0);

    for (int kc = 0; kc < nch; kc++) {
        if (kc + 1 < nch) {
            prefetch((kc + 1) & 1, (kc + 1) * TBK);
            asm volatile("cp.async.wait_group 1;");
        } else {
            asm volatile("cp.async.wait_group 0;");
        }
        __syncthreads();

        const uint32_t sbuf = smem_u32 + (uint32_t)(kc & 1) * (BUF_H * 2);
        const uint32_t sA = sbuf;
        const uint32_t sB = sbuf + A_H * 2;

        #pragma unroll
        for (int kk = 0; kk < 4; kk++) {
            uint32_t af[2][4];
            #pragma unroll
            for (int mt = 0; mt < 2; mt++)
                ldsm_x4(af[mt], sA + (uint32_t)((warpM * 32 + mt * 16 + lrow) * AST
                                                + kk * 16 + lcol) * 2);
            uint32_t bf[2][4];
            #pragma unroll
            for (int n4 = 0; n4 < 2; n4++)
                ldsm_x4_t(bf[n4], sB + (uint32_t)((kk * 16 + lrow) * AST
                                                  + warpN * 32 + n4 * 16 + lcol) * 2);
            #pragma unroll
            for (int mt = 0; mt < 2; mt++)
                #pragma unroll
                for (int nt = 0; nt < 4; nt++) {
                    const int n4 = nt >> 1, sel = (nt & 1) * 2;
                    mma_f16(acc[mt][nt], af[mt], bf[n4][sel], bf[n4][sel + 1]);
                }
        }
        __syncthreads();
    }

    #pragma unroll
    for (int mt = 0; mt < 2; mt++) {
        #pragma unroll
        for (int half = 0; half < 2; half++) {
            const int r = rowBase + warpM * 32 + mt * 16 + half * 8 + g;
            #pragma unroll
            for (int nt = 0; nt < 4; nt++) {
                const int c = colBase + warpN * 32 + nt * 8 + q * 2;
                float v0 = acc[mt][nt][half * 2 + 0];
                float v1 = acc[mt][nt][half * 2 + 1];
                if (EPI == 2) {
                    v0 = fmaxf(v0 + bias[c], 0.0f);
                    v1 = fmaxf(v1 + bias[c + 1], 0.0f);
                }
                *(__half2*)(Cp + (size_t)r * Nn + c) = __floats2half2_rn(v0, v1);
            }
        }
    }
}

// ===========================================================================
// GEMM kernel 2: full-row TBN=128 with fused bias + residual + LayerNorm.
// CTA tile 128x128 (Nn == 128), 8 warps (4M x 2N), warp tile 32x64.
// NORM=true: K=128 fixed; A preloaded whole (sync fill from fp16 attn,
//            divided by denom[row,head]); B double-buffered cp.async.
// NORM=false: A+B chunked double-buffered cp.async (any K).
// RES16: residual read as fp16.  OUT16: write fp16 out, else fp32 out.
// ===========================================================================
#define LST 136                          // halves per smem row (272B) for A-full & B
#define LNA_FULL (TBM * LST)             // 17408 halves (A full, NORM variant)
#define LNB_H (TBK * LST)                // 8704 halves per B buffer
#define LAST 72
#define LA_H (TBM * LAST)                // 9216
#define LBUF_H (LA_H + LNB_H)            // 17920 (non-NORM double buffer unit)
#define GEMMLN_SMEM_BYTES (2 * LBUF_H * 2)  // 71680 (covers both variants)

template <bool NORM, bool RES16, bool OUT16>
__global__ void __launch_bounds__(256, 2)
gemm_ln(const __half* __restrict__ Ap, const __half* __restrict__ Bp,
        const float* __restrict__ bias,
        const float* __restrict__ resf, const __half* __restrict__ resh,
        const float* __restrict__ lng, const float* __restrict__ lnb,
        float* __restrict__ outf, __half* __restrict__ outh,
        const float* __restrict__ dnm, int Kk) {
    extern __shared__ __half sm[];
    const int Nn = HID_;

    const int tid  = threadIdx.x;
    const int wid  = tid >> 5;
    const int lane = tid & 31;
    const int g = lane >> 2;
    const int q = lane & 3;
    const int warpM = wid & 3;
    const int warpN = wid >> 2;
    const int rowBase = blockIdx.y * TBM;

    const uint32_t smem_u32 = (uint32_t)__cvta_generic_to_shared(sm);

    float acc[2][8][4];
    #pragma unroll
    for (int mt = 0; mt < 2; mt++)
        #pragma unroll
        for (int nt = 0; nt < 8; nt++)
            #pragma unroll
            for (int i = 0; i < 4; i++) acc[mt][nt][i] = 0.0f;

    const int lrow = lane & 15;
    const int lcol = (lane >> 4) * 8;
    const int nch = Kk / TBK;

    // B prefetch (both variants); base differs by variant
    auto prefetchB = [&](int buf, int k0) {
        const uint32_t bbase = NORM
            ? smem_u32 + (uint32_t)(LNA_FULL + buf * LNB_H) * 2
            : smem_u32 + (uint32_t)(buf * LBUF_H + LA_H) * 2;
        #pragma unroll
        for (int i = 0; i < 4; i++) {           // B: 64r x 128h = 1024 x 16B
            int idx = tid + i * 256;
            int r   = idx >> 4;
            int c8  = (idx & 15) * 8;
            cp_async16(bbase + (uint32_t)(r * LST + c8) * 2,
                       Bp + (size_t)(k0 + r) * Nn + c8);
        }
        asm volatile("cp.async.commit_group;");
    };
    auto prefetchA = [&](int buf, int k0) {     // non-NORM only
        const uint32_t base = smem_u32 + (uint32_t)(buf * LBUF_H) * 2;
        #pragma unroll
        for (int i = 0; i < 4; i++) {           // A: 128r x 64h = 1024 x 16B
            int idx = tid + i * 256;
            int r   = idx >> 3;
            int c8  = (idx & 7) * 8;
            cp_async16(base + (uint32_t)(r * LAST + c8) * 2,
                       Ap + (size_t)(rowBase + r) * Kk + k0 + c8);
        }
    };

    if (NORM) {
        // Sync-fill the FULL A tile: 128 rows x 128 halves = 2048 uint4 chunks
        // (256 threads x 8 iters). Each uint4 = 8 halves inside ONE head.
        prefetchB(0, 0);
        prefetchB(1, TBK);
        #pragma unroll
        for (int i = 0; i < 8; i++) {
            int idx = tid + i * 256;            // 0..2047
            int r   = idx >> 4;                 // 0..127
            int c8  = (idx & 15) * 8;           // 0,8,...,120
            uint4 raw = *(const uint4*)(Ap + (size_t)(rowBase + r) * HID_ + c8);
            const float inv = 1.0f / fmaxf(dnm[(size_t)(rowBase + r) * H_ + (c8 >> 4)], 1e-6f);
            uint4 o;
            #pragma unroll
            for (int j = 0; j < 4; j++) {
                float2 v = __half22float2(*(__half2*)(((uint32_t*)&raw) + j));
                *(__half2*)(((uint32_t*)&o) + j) = __floats2half2_rn(v.x * inv, v.y * inv);
            }
            *(uint4*)(sm + r * LST + c8) = o;
        }
    } else {
        prefetchA(0, 0);
        prefetchB(0, 0);
    }

    for (int kc = 0; kc < nch; kc++) {
        if (!NORM && kc + 1 < nch) {
            prefetchA((kc + 1) & 1, (kc + 1) * TBK);
            prefetchB((kc + 1) & 1, (kc + 1) * TBK);
        }
        if (NORM) {
            if (kc == 0) asm volatile("cp.async.wait_group 1;");
            else         asm volatile("cp.async.wait_group 0;");
        } else {
            if (kc + 1 < nch) asm volatile("cp.async.wait_group 1;");
            else              asm volatile("cp.async.wait_group 0;");
        }
        __syncthreads();

        const uint32_t sA = NORM ? smem_u32
                                 : smem_u32 + (uint32_t)((kc & 1) * LBUF_H) * 2;
        const uint32_t sB = NORM ? smem_u32 + (uint32_t)(LNA_FULL + (kc & 1) * LNB_H) * 2
                                 : sA + LA_H * 2;
        const int aoff = NORM ? kc * TBK : 0;
        const int astr = NORM ? LST : LAST;

        #pragma unroll
        for (int kk = 0; kk < 4; kk++) {
            uint32_t af[2][4];
            #pragma unroll
            for (int mt = 0; mt < 2; mt++)
                ldsm_x4(af[mt], sA + (uint32_t)((warpM * 32 + mt * 16 + lrow) * astr
                                                + aoff + kk * 16 + lcol) * 2);
            uint32_t bf[4][4];
            #pragma unroll
            for (int n4 = 0; n4 < 4; n4++)
                ldsm_x4_t(bf[n4], sB + (uint32_t)((kk * 16 + lrow) * LST
                                                  + warpN * 64 + n4 * 16 + lcol) * 2);
            #pragma unroll
            for (int mt = 0; mt < 2; mt++)
                #pragma unroll
                for (int nt = 0; nt < 8; nt++) {
                    const int n4 = nt >> 1, sel = (nt & 1) * 2;
                    mma_f16(acc[mt][nt], af[mt], bf[n4][sel], bf[n4][sel + 1]);
                }
        }
        if (NORM) {
            if (kc + 1 < nch) __syncthreads();
        } else {
            __syncthreads();
        }
    }

    // ---- LN epilogue ----
    float* red = (float*)sm;
    __syncthreads();

    #pragma unroll
    for (int mt = 0; mt < 2; mt++) {
        #pragma unroll
        for (int half = 0; half < 2; half++) {
            const int r = rowBase + warpM * 32 + mt * 16 + half * 8 + g;
            float s1 = 0.0f, s2 = 0.0f;
            #pragma unroll
            for (int nt = 0; nt < 8; nt++) {
                const int c = warpN * 64 + nt * 8 + q * 2;
                float r0, r1;
                if (RES16) {
                    float2 rr = __half22float2(*(const __half2*)(resh + (size_t)r * Nn + c));
                    r0 = rr.x; r1 = rr.y;
                } else {
                    const float2 rr = *(const float2*)(resf + (size_t)r * Nn + c);
                    r0 = rr.x; r1 = rr.y;
                }
                float v0 = acc[mt][nt][half * 2 + 0] + bias[c]     + r0;
                float v1 = acc[mt][nt][half * 2 + 1] + bias[c + 1] + r1;
                acc[mt][nt][half * 2 + 0] = v0;
                acc[mt][nt][half * 2 + 1] = v1;
                s1 += v0 + v1;
                s2 += v0 * v0 + v1 * v1;
            }
            s1 += __shfl_xor_sync(0xFFFFFFFFu, s1, 1);
            s1 += __shfl_xor_sync(0xFFFFFFFFu, s1, 2);
            s2 += __shfl_xor_sync(0xFFFFFFFFu, s2, 1);
            s2 += __shfl_xor_sync(0xFFFFFFFFu, s2, 2);
            if (q == 0) {
                const int idx = ((((warpM * 2 + mt) * 2 + half) * 8 + g) * 2 + warpN);
                red[idx * 2 + 0] = s1;
                red[idx * 2 + 1] = s2;
            }
        }
    }
    __syncthreads();

    #pragma unroll
    for (int mt = 0; mt < 2; mt++) {
        #pragma unroll
        for (int half = 0; half < 2; half++) {
            const int r = rowBase + warpM * 32 + mt * 16 + half * 8 + g;
            const int ibase = ((((warpM * 2 + mt) * 2 + half) * 8 + g) * 2);
            const float sum = red[ibase * 2 + 0] + red[(ibase + 1) * 2 + 0];
            const float sq  = red[ibase * 2 + 1] + red[(ibase + 1) * 2 + 1];
            const float mean = sum * (1.0f / 128.0f);
            const float var  = sq * (1.0f / 128.0f) - mean * mean;
            const float rs   = rsqrtf(var + 1e-5f);
            #pragma unroll
            for (int nt = 0; nt < 8; nt++) {
                const int c = warpN * 64 + nt * 8 + q * 2;
                const float o0 = (acc[mt][nt][half * 2 + 0] - mean) * rs * lng[c]     + lnb[c];
                const float o1 = (acc[mt][nt][half * 2 + 1] - mean) * rs * lng[c + 1] + lnb[c + 1];
                if (OUT16) {
                    *(__half2*)(outh + (size_t)r * Nn + c) = __floats2half2_rn(o0, o1);
                } else {
                    float2 of = {o0, o1};
                    *(float2*)(outf + (size_t)r * Nn + c) = of;
                }
            }
        }
    }
}

// ---------------------------------------------------------------------------
// Fused edge pass: logits -> p = exp -> denom += p, attn16[dst] += p * V[src]
// (fp16 atomics). FOUR edges per warp; lane -> head = lane/4, dv = lane%4.
// QKV fp16 packed per row: Q +0, K +128, V +256.
// ---------------------------------------------------------------------------
__global__ void __launch_bounds__(256)
edge_attn_kernel(const __half* __restrict__ QKV,
                 const float* __restrict__ ef, const int* __restrict__ eidx,
                 const int* __restrict__ nE, const float* __restrict__ We,
                 float* __restrict__ denom, __half* __restrict__ attn16) {
    const int w = (blockIdx.x * blockDim.x + threadIdx.x) >> 5;
    const int lane = threadIdx.x & 31;
    const int b = w >> 15;              // E_/4 = 32768 warps per batch
    const int e0 = (w & 32767) * 4;
    const int ne = nE[b];
    if (e0 >= ne) return;
    const int cnt = min(4, ne - e0);

    const int head = lane >> 2;
    const int dv = lane & 3;
    const int hoff = head * D_ + dv * 4;

    const size_t ebase = (size_t)b * 2 * E_;
    const int4 srcs = *(const int4*)(eidx + ebase + e0);
    const int4 dsts = *(const int4*)(eidx + ebase + E_ + e0);
    const int src[4] = {srcs.x, srcs.y, srcs.z, srcs.w};
    const int dst[4] = {dsts.x, dsts.y, dsts.z, dsts.w};

    uint2 qv[4], kv[4], vv[4];
    #pragma unroll
    for (int i = 0; i < 4; i++) {
        const __half* qp = QKV + ((size_t)(b * N_ + dst[i])) * HID3 + hoff;
        const __half* kp = QKV + ((size_t)(b * N_ + src[i])) * HID3 + 128 + hoff;
        qv[i] = *(const uint2*)qp;
        kv[i] = *(const uint2*)kp;
        vv[i] = *(const uint2*)(kp + 128);
    }
    const float4 ef01 = *(const float4*)(ef + ((size_t)b * E_ + e0) * 2);
    const float4 ef23 = *(const float4*)(ef + ((size_t)b * E_ + e0) * 2 + 4);
    const float we0 = __ldg(We + head);
    const float we1 = __ldg(We + H_ + head);
    const float efe[4][2] = {{ef01.x, ef01.y}, {ef01.z, ef01.w},
                             {ef23.x, ef23.y}, {ef23.z, ef23.w}};

    float s[4];
    #pragma unroll
    for (int i = 0; i < 4; i++) s[i] = dot4h(qv[i], kv[i]);
    #pragma unroll
    for (int i = 0; i < 4; i++) {
        s[i] += __shfl_xor_sync(0xFFFFFFFFu, s[i], 1);
        s[i] += __shfl_xor_sync(0xFFFFFFFFu, s[i], 2);
    }

    #pragma unroll
    for (int i = 0; i < 4; i++) {
        if (i >= cnt) break;
        const float p = __expf(s[i] * 0.25f + efe[i][0] * we0 + efe[i][1] * we1);
        if (dv == 0)
            atomicAdd(denom + ((size_t)(b * N_ + dst[i])) * H_ + head, p);
        float2 a = __half22float2(*(__half2*)&vv[i].x);
        float2 c = __half22float2(*(__half2*)&vv[i].y);
        uint32_t pv0, pv1;
        *(__half2*)&pv0 = __floats2half2_rn(p * a.x, p * a.y);
        *(__half2*)&pv1 = __floats2half2_rn(p * c.x, p * c.y);
        __half* out = attn16 + ((size_t)(b * N_ + dst[i])) * HID_ + hoff;
        asm volatile("red.global.add.noftz.f16x2 [%0], %1;"
                     :: "l"(out), "r"(pv0) : "memory");
        asm volatile("red.global.add.noftz.f16x2 [%0], %1;"
                     :: "l"(out + 2), "r"(pv1) : "memory");
    }
}

// ---------------------------------------------------------------------------
// Launch
// ---------------------------------------------------------------------------
extern "C" void kernel_launch(void* const* d_in, const int* in_sizes, int n_in,
                              void* d_out, int out_size) {
    const float* h    = (const float*)d_in[0];
    const float* ef   = (const float*)d_in[1];
    const int*   eidx = (const int*)d_in[2];
    const int*   nE   = (const int*)d_in[3];
    const float* Wq   = (const float*)d_in[4];
    const float* Wk   = (const float*)d_in[5];
    const float* Wv   = (const float*)d_in[6];
    const float* Wo   = (const float*)d_in[7];
    const float* bo   = (const float*)d_in[8];
    const float* We   = (const float*)d_in[9];
    const float* ln1g = (const float*)d_in[10];
    const float* ln1b = (const float*)d_in[11];
    const float* ln2g = (const float*)d_in[12];
    const float* ln2b = (const float*)d_in[13];
    const float* ff1  = (const float*)d_in[14];
    const float* b1   = (const float*)d_in[15];
    const float* ff2  = (const float*)d_in[16];
    const float* b2   = (const float*)d_in[17];
    float* out = (float*)d_out;

    float *dn;
    __half *h16, *QKV16, *attn16, *hmid16, *ffb, *w16;
    cudaGetSymbolAddress((void**)&h16, g_h16);
    cudaGetSymbolAddress((void**)&QKV16, g_QKV16);
    cudaGetSymbolAddress((void**)&dn, g_denom);
    cudaGetSymbolAddress((void**)&attn16, g_attn16);
    cudaGetSymbolAddress((void**)&hmid16, g_hmid16);
    cudaGetSymbolAddress((void**)&ffb, g_ff16);
    cudaGetSymbolAddress((void**)&w16, g_w16);

    static bool attr_done = false;
    if (!attr_done) {
        cudaFuncSetAttribute((const void*)gemm_h<2>, cudaFuncAttributeMaxDynamicSharedMemorySize, GEMM_SMEM_BYTES);
        cudaFuncSetAttribute((const void*)gemm_h<3>, cudaFuncAttributeMaxDynamicSharedMemorySize, GEMM_SMEM_BYTES);
        cudaFuncSetAttribute((const void*)gemm_ln<true, false, true>,   cudaFuncAttributeMaxDynamicSharedMemorySize, GEMMLN_SMEM_BYTES);
        cudaFuncSetAttribute((const void*)gemm_ln<false, true, false>,  cudaFuncAttributeMaxDynamicSharedMemorySize, GEMMLN_SMEM_BYTES);
        attr_done = true;
    }

    // 0. weight pack; fused prologue (h->fp16, attn16=0, denom=0)
    prep_w16_kernel<<<512, 256>>>(Wq, Wk, Wv, Wo, ff1, ff2, w16);
    prologue_kernel<<<(M_ * HID_ / 4) / 256, 256>>>(h, h16, attn16, dn);

    // 1. fused QKV projection -> fp16 QKV
    dim3 gq(HID3 / TBN, M_ / TBM);             // (6, 512)
    gemm_h<3><<<gq, 256, GEMM_SMEM_BYTES>>>(h16, w16 + W16_QKV, nullptr, QKV16, HID_, HID3);

    // 2. fused edge pass: logits + exp + denom + fp16 scatter
    edge_attn_kernel<<<(B_ * E_) / 32, 256>>>(QKV16, ef, eidx, nE, We, dn, attn16);

    // 3. Wo GEMM (A = attn16 / denom, normalized in fill) + bias + residual(h)
    //    + LN1 fused -> hmid16 (fp16 only)
    dim3 gl(1, M_ / TBM);
    gemm_ln<true, false, true><<<gl, 256, GEMMLN_SMEM_BYTES>>>(
        attn16, w16 + W16_WO, bo, h, nullptr, ln1g, ln1b, nullptr, hmid16, dn, HID_);

    // 4. ff1 (+bias+relu -> fp16)
    dim3 g2(2 * HID_ / TBN, M_ / TBM);         // (4, 512)
    gemm_h<2><<<g2, 256, GEMM_SMEM_BYTES>>>(hmid16, w16 + W16_FF1, b1, ffb, HID_, 2 * HID_);

    // 5. ff2 GEMM + bias + residual(hmid16) + LN2 fused -> out (fp32)
    gemm_ln<false, true, false><<<gl, 256, GEMMLN_SMEM_BYTES>>>(
        ffb, w16 + W16_FF2, b2, nullptr, hmid16, ln2g, ln2b, out, nullptr, nullptr, 2 * HID_);
}

// round 16
// speedup vs baseline: 1.2136x; 1.0073x over previous
#include <cuda_runtime.h>
#include <cuda_fp16.h>
#include <cstddef>
#include <cstdint>

// Problem constants
#define B_   4
#define N_   16384
#define E_   131072
#define HID_ 128
#define H_   8
#define D_   16
#define M_   (B_ * N_)   // 65536 flattened rows
#define HID3 384

// ---------------------------------------------------------------------------
// Scratch (device globals; no allocations allowed)
// ---------------------------------------------------------------------------
__device__ __half g_h16[(size_t)M_ * HID_];          // h in fp16 (QKV A)
__device__ __half g_QKV16[(size_t)M_ * HID3];        // Q|K|V packed per row, fp16
__device__ float  g_denom[(size_t)B_ * N_ * H_];
__device__ __half g_attn16[(size_t)M_ * HID_];       // fp16 Σ p·V (atomic target)
__device__ __half g_hmid16[(size_t)M_ * HID_];       // LN1 out, fp16
__device__ __half g_ff16[(size_t)M_ * 2 * HID_];     // ff1 output (fp16)
__device__ __half g_w16[49152 + 16384 + 32768 + 32768]; // packed fp16 weights

#define W16_QKV 0
#define W16_WO  49152
#define W16_FF1 65536
#define W16_FF2 98304

// ---------------------------------------------------------------------------
// Helpers
// ---------------------------------------------------------------------------
__device__ __forceinline__ void cp_async16(uint32_t s, const void* g) {
    asm volatile("cp.async.cg.shared.global [%0], [%1], 16;" :: "r"(s), "l"(g));
}

__device__ __forceinline__ void ldsm_x4(uint32_t* r, uint32_t addr) {
    asm volatile("ldmatrix.sync.aligned.m8n8.x4.shared.b16 {%0,%1,%2,%3}, [%4];"
                 : "=r"(r[0]), "=r"(r[1]), "=r"(r[2]), "=r"(r[3]) : "r"(addr));
}
__device__ __forceinline__ void ldsm_x4_t(uint32_t* r, uint32_t addr) {
    asm volatile("ldmatrix.sync.aligned.m8n8.x4.trans.shared.b16 {%0,%1,%2,%3}, [%4];"
                 : "=r"(r[0]), "=r"(r[1]), "=r"(r[2]), "=r"(r[3]) : "r"(addr));
}
__device__ __forceinline__ void mma_f16(float* d, const uint32_t* a, uint32_t b0, uint32_t b1) {
    asm volatile(
        "mma.sync.aligned.m16n8k16.row.col.f32.f16.f16.f32 "
        "{%0,%1,%2,%3}, {%4,%5,%6,%7}, {%8,%9}, {%0,%1,%2,%3};"
        : "+f"(d[0]), "+f"(d[1]), "+f"(d[2]), "+f"(d[3])
        : "r"(a[0]), "r"(a[1]), "r"(a[2]), "r"(a[3]), "r"(b0), "r"(b1));
}

// dot of 4 fp16 pairs (as uint2) in fp32
__device__ __forceinline__ float dot4h(uint2 qa, uint2 ka) {
    float2 q0 = __half22float2(*(__half2*)&qa.x);
    float2 q1 = __half22float2(*(__half2*)&qa.y);
    float2 k0 = __half22float2(*(__half2*)&ka.x);
    float2 k1 = __half22float2(*(__half2*)&ka.y);
    return q0.x * k0.x + q0.y * k0.y + q1.x * k1.x + q1.y * k1.y;
}

// ---------------------------------------------------------------------------
// Fused prologue: weight pack (fp32->fp16), h->fp16, attn16=0, denom=0.
// Grid: 8192 x 256 threads (covers M_*HID_/4 = 2,097,152 float4 slots).
// Weight pack handled by the first 131072 threads; denom by first 524288.
// ---------------------------------------------------------------------------
__global__ void __launch_bounds__(256)
prologue_kernel(const float* __restrict__ h, __half* __restrict__ h16,
                __half* __restrict__ attn16, float* __restrict__ denom,
                const float* __restrict__ Wq, const float* __restrict__ Wk,
                const float* __restrict__ Wv, const float* __restrict__ Wo,
                const float* __restrict__ ff1, const float* __restrict__ ff2,
                __half* __restrict__ w16) {
    const size_t i = (size_t)blockIdx.x * blockDim.x + threadIdx.x; // M_*HID_/4
    const size_t off = i * 4;
    float4 v = *(const float4*)(h + off);
    uint2 o;
    *(__half2*)&o.x = __floats2half2_rn(v.x, v.y);
    *(__half2*)&o.y = __floats2half2_rn(v.z, v.w);
    *(uint2*)(h16 + off) = o;
    uint2 z = {0u, 0u};
    *(uint2*)(attn16 + off) = z;
    if (i < (size_t)B_ * N_ * H_) denom[i] = 0.0f;
    const int idx = (int)i;
    if (idx < 131072) {
        float wv;
        if (idx < 49152) {
            int k = idx / HID3, j = idx % HID3;
            wv = (j < 128) ? Wq[k * 128 + j]
               : (j < 256) ? Wk[k * 128 + j - 128]
                           : Wv[k * 128 + j - 256];
        } else if (idx < 65536) {
            wv = Wo[idx - 49152];
        } else if (idx < 98304) {
            wv = ff1[idx - 65536];
        } else {
            wv = ff2[idx - 98304];
        }
        w16[idx] = __float2half(wv);
    }
}

// ===========================================================================
// GEMM kernel 1: wide-N, 3-stage TBK=32 pipeline, occ-4 (for QKV and ff1)
// CTA tile 128x64, 8 warps (4M x 2N), warp tile 32x32, mma.m16n8k16.
// Prefetch distance 2: two chunks in flight while computing.
// EPI: 2 = +bias+relu (f16 out), 3 = none (f16 out)
// ===========================================================================
#define TBM 128
#define TBN 64
#define S3K 32
#define S3A 40                            // A smem stride (halves); 20 words = conflict-free
#define S3B 72                            // B smem stride (halves); 36 words = conflict-free
#define S3A_H (TBM * S3A)                 // 5120 halves
#define S3B_H (S3K * S3B)                 // 2304 halves
#define S3BUF (S3A_H + S3B_H)             // 7424 halves per stage
#define GEMM_SMEM_BYTES (3 * S3BUF * 2)   // 44544 B

template <int EPI>
__global__ void __launch_bounds__(256, 4)
gemm_h(const __half* __restrict__ Ap, const __half* __restrict__ Bp,
       const float* __restrict__ bias, __half* __restrict__ Cp,
       int Kk, int Nn) {
    extern __shared__ __half sm[];

    const int tid  = threadIdx.x;
    const int wid  = tid >> 5;
    const int lane = tid & 31;
    const int g = lane >> 2;
    const int q = lane & 3;
    const int warpM = wid & 3;
    const int warpN = wid >> 2;
    const int rowBase = blockIdx.y * TBM;
    const int colBase = blockIdx.x * TBN;

    const uint32_t smem_u32 = (uint32_t)__cvta_generic_to_shared(sm);

    float acc[2][4][4];
    #pragma unroll
    for (int mt = 0; mt < 2; mt++)
        #pragma unroll
        for (int nt = 0; nt < 4; nt++)
            #pragma unroll
            for (int i = 0; i < 4; i++) acc[mt][nt][i] = 0.0f;

    const int lrow = lane & 15;
    const int lcol = (lane >> 4) * 8;
    const int nch = Kk / S3K;

    auto prefetch = [&](int stage, int k0) {
        const uint32_t base = smem_u32 + (uint32_t)stage * (S3BUF * 2);
        // A: 128 rows x 32 halves = 512 x 8-half chunks (256 thr x 2)
        #pragma unroll
        for (int i = 0; i < 2; i++) {
            int idx = tid + i * 256;
            int r   = idx >> 2;
            int c8  = (idx & 3) * 8;
            cp_async16(base + (uint32_t)(r * S3A + c8) * 2,
                       Ap + (size_t)(rowBase + r) * Kk + k0 + c8);
        }
        // B: 32 rows x 64 halves = 256 x 8-half chunks (256 thr x 1)
        const uint32_t bbase = base + S3A_H * 2;
        {
            int idx = tid;
            int r   = idx >> 3;
            int c8  = (idx & 7) * 8;
            cp_async16(bbase + (uint32_t)(r * S3B + c8) * 2,
                       Bp + (size_t)(k0 + r) * Nn + colBase + c8);
        }
        asm volatile("cp.async.commit_group;");
    };

    prefetch(0, 0);
    if (nch > 1) prefetch(1, S3K);

    int stage = 0;
    for (int kc = 0; kc < nch; kc++) {
        // stage (kc+2)%3 was last read at iteration kc-1; the end-of-loop
        // __syncthreads below protects the overwrite.
        if (kc + 2 < nch) prefetch((kc + 2) % 3, (kc + 2) * S3K);
        const int pend = nch - 1 - kc;
        if (pend >= 2)      asm volatile("cp.async.wait_group 2;");
        else if (pend == 1) asm volatile("cp.async.wait_group 1;");
        else                asm volatile("cp.async.wait_group 0;");
        __syncthreads();

        const uint32_t sbuf = smem_u32 + (uint32_t)stage * (S3BUF * 2);
        const uint32_t sA = sbuf;
        const uint32_t sB = sbuf + S3A_H * 2;

        #pragma unroll
        for (int kk = 0; kk < 2; kk++) {
            uint32_t af[2][4];
            #pragma unroll
            for (int mt = 0; mt < 2; mt++)
                ldsm_x4(af[mt], sA + (uint32_t)((warpM * 32 + mt * 16 + lrow) * S3A
                                                + kk * 16 + lcol) * 2);
            uint32_t bf[2][4];
            #pragma unroll
            for (int n4 = 0; n4 < 2; n4++)
                ldsm_x4_t(bf[n4], sB + (uint32_t)((kk * 16 + lrow) * S3B
                                                  + warpN * 32 + n4 * 16 + lcol) * 2);
            #pragma unroll
            for (int mt = 0; mt < 2; mt++)
                #pragma unroll
                for (int nt = 0; nt < 4; nt++) {
                    const int n4 = nt >> 1, sel = (nt & 1) * 2;
                    mma_f16(acc[mt][nt], af[mt], bf[n4][sel], bf[n4][sel + 1]);
                }
        }
        if (kc + 1 < nch) __syncthreads();
        stage = (stage + 1 == 3) ? 0 : stage + 1;
    }

    #pragma unroll
    for (int mt = 0; mt < 2; mt++) {
        #pragma unroll
        for (int half = 0; half < 2; half++) {
            const int r = rowBase + warpM * 32 + mt * 16 + half * 8 + g;
            #pragma unroll
            for (int nt = 0; nt < 4; nt++) {
                const int c = colBase + warpN * 32 + nt * 8 + q * 2;
                float v0 = acc[mt][nt][half * 2 + 0];
                float v1 = acc[mt][nt][half * 2 + 1];
                if (EPI == 2) {
                    v0 = fmaxf(v0 + bias[c], 0.0f);
                    v1 = fmaxf(v1 + bias[c + 1], 0.0f);
                }
                *(__half2*)(Cp + (size_t)r * Nn + c) = __floats2half2_rn(v0, v1);
            }
        }
    }
}

// ===========================================================================
// GEMM kernel 2: full-row TBN=128 with fused bias + residual + LayerNorm.
// CTA tile 128x128 (Nn == 128), 8 warps (4M x 2N), warp tile 32x64, TBK=64.
// NORM=true: K=128 fixed; A preloaded whole (sync fill from fp16 attn,
//            divided by denom[row,head]); B double-buffered cp.async.
// NORM=false: A+B chunked double-buffered cp.async (any K).
// RES16: residual read as fp16.  OUT16: write fp16 out, else fp32 out.
// ===========================================================================
#define TBK 64
#define LST 136                          // halves per smem row (272B) for A-full & B
#define LNA_FULL (TBM * LST)             // 17408 halves (A full, NORM variant)
#define LNB_H (TBK * LST)                // 8704 halves per B buffer
#define LAST 72
#define LA_H (TBM * LAST)                // 9216
#define LBUF_H (LA_H + LNB_H)            // 17920 (non-NORM double buffer unit)
#define GEMMLN_SMEM_BYTES (2 * LBUF_H * 2)  // 71680 (covers both variants)

template <bool NORM, bool RES16, bool OUT16>
__global__ void __launch_bounds__(256, 2)
gemm_ln(const __half* __restrict__ Ap, const __half* __restrict__ Bp,
        const float* __restrict__ bias,
        const float* __restrict__ resf, const __half* __restrict__ resh,
        const float* __restrict__ lng, const float* __restrict__ lnb,
        float* __restrict__ outf, __half* __restrict__ outh,
        const float* __restrict__ dnm, int Kk) {
    extern __shared__ __half sm[];
    const int Nn = HID_;

    const int tid  = threadIdx.x;
    const int wid  = tid >> 5;
    const int lane = tid & 31;
    const int g = lane >> 2;
    const int q = lane & 3;
    const int warpM = wid & 3;
    const int warpN = wid >> 2;
    const int rowBase = blockIdx.y * TBM;

    const uint32_t smem_u32 = (uint32_t)__cvta_generic_to_shared(sm);

    float acc[2][8][4];
    #pragma unroll
    for (int mt = 0; mt < 2; mt++)
        #pragma unroll
        for (int nt = 0; nt < 8; nt++)
            #pragma unroll
            for (int i = 0; i < 4; i++) acc[mt][nt][i] = 0.0f;

    const int lrow = lane & 15;
    const int lcol = (lane >> 4) * 8;
    const int nch = Kk / TBK;

    auto prefetchB = [&](int buf, int k0) {
        const uint32_t bbase = NORM
            ? smem_u32 + (uint32_t)(LNA_FULL + buf * LNB_H) * 2
            : smem_u32 + (uint32_t)(buf * LBUF_H + LA_H) * 2;
        #pragma unroll
        for (int i = 0; i < 4; i++) {           // B: 64r x 128h = 1024 x 16B
            int idx = tid + i * 256;
            int r   = idx >> 4;
            int c8  = (idx & 15) * 8;
            cp_async16(bbase + (uint32_t)(r * LST + c8) * 2,
                       Bp + (size_t)(k0 + r) * Nn + c8);
        }
        asm volatile("cp.async.commit_group;");
    };
    auto prefetchA = [&](int buf, int k0) {     // non-NORM only
        const uint32_t base = smem_u32 + (uint32_t)(buf * LBUF_H) * 2;
        #pragma unroll
        for (int i = 0; i < 4; i++) {           // A: 128r x 64h = 1024 x 16B
            int idx = tid + i * 256;
            int r   = idx >> 3;
            int c8  = (idx & 7) * 8;
            cp_async16(base + (uint32_t)(r * LAST + c8) * 2,
                       Ap + (size_t)(rowBase + r) * Kk + k0 + c8);
        }
    };

    if (NORM) {
        // Sync-fill the FULL A tile: 128 rows x 128 halves = 2048 uint4 chunks
        // (256 threads x 8 iters). Each uint4 = 8 halves inside ONE head.
        prefetchB(0, 0);
        prefetchB(1, TBK);
        #pragma unroll
        for (int i = 0; i < 8; i++) {
            int idx = tid + i * 256;            // 0..2047
            int r   = idx >> 4;                 // 0..127
            int c8  = (idx & 15) * 8;           // 0,8,...,120
            uint4 raw = *(const uint4*)(Ap + (size_t)(rowBase + r) * HID_ + c8);
            const float inv = 1.0f / fmaxf(dnm[(size_t)(rowBase + r) * H_ + (c8 >> 4)], 1e-6f);
            uint4 o;
            #pragma unroll
            for (int j = 0; j < 4; j++) {
                float2 v = __half22float2(*(__half2*)(((uint32_t*)&raw) + j));
                *(__half2*)(((uint32_t*)&o) + j) = __floats2half2_rn(v.x * inv, v.y * inv);
            }
            *(uint4*)(sm + r * LST + c8) = o;
        }
    } else {
        prefetchA(0, 0);
        prefetchB(0, 0);
    }

    for (int kc = 0; kc < nch; kc++) {
        if (!NORM && kc + 1 < nch) {
            prefetchA((kc + 1) & 1, (kc + 1) * TBK);
            prefetchB((kc + 1) & 1, (kc + 1) * TBK);
        }
        if (NORM) {
            if (kc == 0) asm volatile("cp.async.wait_group 1;");
            else         asm volatile("cp.async.wait_group 0;");
        } else {
            if (kc + 1 < nch) asm volatile("cp.async.wait_group 1;");
            else              asm volatile("cp.async.wait_group 0;");
        }
        __syncthreads();

        const uint32_t sA = NORM ? smem_u32
                                 : smem_u32 + (uint32_t)((kc & 1) * LBUF_H) * 2;
        const uint32_t sB = NORM ? smem_u32 + (uint32_t)(LNA_FULL + (kc & 1) * LNB_H) * 2
                                 : sA + LA_H * 2;
        const int aoff = NORM ? kc * TBK : 0;
        const int astr = NORM ? LST : LAST;

        #pragma unroll
        for (int kk = 0; kk < 4; kk++) {
            uint32_t af[2][4];
            #pragma unroll
            for (int mt = 0; mt < 2; mt++)
                ldsm_x4(af[mt], sA + (uint32_t)((warpM * 32 + mt * 16 + lrow) * astr
                                                + aoff + kk * 16 + lcol) * 2);
            uint32_t bf[4][4];
            #pragma unroll
            for (int n4 = 0; n4 < 4; n4++)
                ldsm_x4_t(bf[n4], sB + (uint32_t)((kk * 16 + lrow) * LST
                                                  + warpN * 64 + n4 * 16 + lcol) * 2);
            #pragma unroll
            for (int mt = 0; mt < 2; mt++)
                #pragma unroll
                for (int nt = 0; nt < 8; nt++) {
                    const int n4 = nt >> 1, sel = (nt & 1) * 2;
                    mma_f16(acc[mt][nt], af[mt], bf[n4][sel], bf[n4][sel + 1]);
                }
        }
        if (NORM) {
            if (kc + 1 < nch) __syncthreads();
        } else {
            __syncthreads();
        }
    }

    // ---- LN epilogue ----
    float* red = (float*)sm;
    __syncthreads();

    #pragma unroll
    for (int mt = 0; mt < 2; mt++) {
        #pragma unroll
        for (int half = 0; half < 2; half++) {
            const int r = rowBase + warpM * 32 + mt * 16 + half * 8 + g;
            float s1 = 0.0f, s2 = 0.0f;
            #pragma unroll
            for (int nt = 0; nt < 8; nt++) {
                const int c = warpN * 64 + nt * 8 + q * 2;
                float r0, r1;
                if (RES16) {
                    float2 rr = __half22float2(*(const __half2*)(resh + (size_t)r * Nn + c));
                    r0 = rr.x; r1 = rr.y;
                } else {
                    const float2 rr = *(const float2*)(resf + (size_t)r * Nn + c);
                    r0 = rr.x; r1 = rr.y;
                }
                float v0 = acc[mt][nt][half * 2 + 0] + bias[c]     + r0;
                float v1 = acc[mt][nt][half * 2 + 1] + bias[c + 1] + r1;
                acc[mt][nt][half * 2 + 0] = v0;
                acc[mt][nt][half * 2 + 1] = v1;
                s1 += v0 + v1;
                s2 += v0 * v0 + v1 * v1;
            }
            s1 += __shfl_xor_sync(0xFFFFFFFFu, s1, 1);
            s1 += __shfl_xor_sync(0xFFFFFFFFu, s1, 2);
            s2 += __shfl_xor_sync(0xFFFFFFFFu, s2, 1);
            s2 += __shfl_xor_sync(0xFFFFFFFFu, s2, 2);
            if (q == 0) {
                const int idx = ((((warpM * 2 + mt) * 2 + half) * 8 + g) * 2 + warpN);
                red[idx * 2 + 0] = s1;
                red[idx * 2 + 1] = s2;
            }
        }
    }
    __syncthreads();

    #pragma unroll
    for (int mt = 0; mt < 2; mt++) {
        #pragma unroll
        for (int half = 0; half < 2; half++) {
            const int r = rowBase + warpM * 32 + mt * 16 + half * 8 + g;
            const int ibase = ((((warpM * 2 + mt) * 2 + half) * 8 + g) * 2);
            const float sum = red[ibase * 2 + 0] + red[(ibase + 1) * 2 + 0];
            const float sq  = red[ibase * 2 + 1] + red[(ibase + 1) * 2 + 1];
            const float mean = sum * (1.0f / 128.0f);
            const float var  = sq * (1.0f / 128.0f) - mean * mean;
            const float rs   = rsqrtf(var + 1e-5f);
            #pragma unroll
            for (int nt = 0; nt < 8; nt++) {
                const int c = warpN * 64 + nt * 8 + q * 2;
                const float o0 = (acc[mt][nt][half * 2 + 0] - mean) * rs * lng[c]     + lnb[c];
                const float o1 = (acc[mt][nt][half * 2 + 1] - mean) * rs * lng[c + 1] + lnb[c + 1];
                if (OUT16) {
                    *(__half2*)(outh + (size_t)r * Nn + c) = __floats2half2_rn(o0, o1);
                } else {
                    float2 of = {o0, o1};
                    *(float2*)(outf + (size_t)r * Nn + c) = of;
                }
            }
        }
    }
}

// ---------------------------------------------------------------------------
// Fused edge pass: logits -> p = exp -> denom += p, attn16[dst] += p * V[src]
// (fp16 atomics). FOUR edges per warp; lane -> head = lane/4, dv = lane%4.
// QKV fp16 packed per row: Q +0, K +128, V +256.
// ---------------------------------------------------------------------------
__global__ void __launch_bounds__(256)
edge_attn_kernel(const __half* __restrict__ QKV,
                 const float* __restrict__ ef, const int* __restrict__ eidx,
                 const int* __restrict__ nE, const float* __restrict__ We,
                 float* __restrict__ denom, __half* __restrict__ attn16) {
    const int w = (blockIdx.x * blockDim.x + threadIdx.x) >> 5;
    const int lane = threadIdx.x & 31;
    const int b = w >> 15;              // E_/4 = 32768 warps per batch
    const int e0 = (w & 32767) * 4;
    const int ne = nE[b];
    if (e0 >= ne) return;
    const int cnt = min(4, ne - e0);

    const int head = lane >> 2;
    const int dv = lane & 3;
    const int hoff = head * D_ + dv * 4;

    const size_t ebase = (size_t)b * 2 * E_;
    const int4 srcs = *(const int4*)(eidx + ebase + e0);
    const int4 dsts = *(const int4*)(eidx + ebase + E_ + e0);
    const int src[4] = {srcs.x, srcs.y, srcs.z, srcs.w};
    const int dst[4] = {dsts.x, dsts.y, dsts.z, dsts.w};

    uint2 qv[4], kv[4], vv[4];
    #pragma unroll
    for (int i = 0; i < 4; i++) {
        const __half* qp = QKV + ((size_t)(b * N_ + dst[i])) * HID3 + hoff;
        const __half* kp = QKV + ((size_t)(b * N_ + src[i])) * HID3 + 128 + hoff;
        qv[i] = *(const uint2*)qp;
        kv[i] = *(const uint2*)kp;
        vv[i] = *(const uint2*)(kp + 128);
    }
    const float4 ef01 = *(const float4*)(ef + ((size_t)b * E_ + e0) * 2);
    const float4 ef23 = *(const float4*)(ef + ((size_t)b * E_ + e0) * 2 + 4);
    const float we0 = __ldg(We + head);
    const float we1 = __ldg(We + H_ + head);
    const float efe[4][2] = {{ef01.x, ef01.y}, {ef01.z, ef01.w},
                             {ef23.x, ef23.y}, {ef23.z, ef23.w}};

    float s[4];
    #pragma unroll
    for (int i = 0; i < 4; i++) s[i] = dot4h(qv[i], kv[i]);
    #pragma unroll
    for (int i = 0; i < 4; i++) {
        s[i] += __shfl_xor_sync(0xFFFFFFFFu, s[i], 1);
        s[i] += __shfl_xor_sync(0xFFFFFFFFu, s[i], 2);
    }

    #pragma unroll
    for (int i = 0; i < 4; i++) {
        if (i >= cnt) break;
        const float p = __expf(s[i] * 0.25f + efe[i][0] * we0 + efe[i][1] * we1);
        if (dv == 0)
            atomicAdd(denom + ((size_t)(b * N_ + dst[i])) * H_ + head, p);
        float2 a = __half22float2(*(__half2*)&vv[i].x);
        float2 c = __half22float2(*(__half2*)&vv[i].y);
        uint32_t pv0, pv1;
        *(__half2*)&pv0 = __floats2half2_rn(p * a.x, p * a.y);
        *(__half2*)&pv1 = __floats2half2_rn(p * c.x, p * c.y);
        __half* out = attn16 + ((size_t)(b * N_ + dst[i])) * HID_ + hoff;
        asm volatile("red.global.add.noftz.f16x2 [%0], %1;"
                     :: "l"(out), "r"(pv0) : "memory");
        asm volatile("red.global.add.noftz.f16x2 [%0], %1;"
                     :: "l"(out + 2), "r"(pv1) : "memory");
    }
}

// ---------------------------------------------------------------------------
// Launch
// ---------------------------------------------------------------------------
extern "C" void kernel_launch(void* const* d_in, const int* in_sizes, int n_in,
                              void* d_out, int out_size) {
    const float* h    = (const float*)d_in[0];
    const float* ef   = (const float*)d_in[1];
    const int*   eidx = (const int*)d_in[2];
    const int*   nE   = (const int*)d_in[3];
    const float* Wq   = (const float*)d_in[4];
    const float* Wk   = (const float*)d_in[5];
    const float* Wv   = (const float*)d_in[6];
    const float* Wo   = (const float*)d_in[7];
    const float* bo   = (const float*)d_in[8];
    const float* We   = (const float*)d_in[9];
    const float* ln1g = (const float*)d_in[10];
    const float* ln1b = (const float*)d_in[11];
    const float* ln2g = (const float*)d_in[12];
    const float* ln2b = (const float*)d_in[13];
    const float* ff1  = (const float*)d_in[14];
    const float* b1   = (const float*)d_in[15];
    const float* ff2  = (const float*)d_in[16];
    const float* b2   = (const float*)d_in[17];
    float* out = (float*)d_out;

    float *dn;
    __half *h16, *QKV16, *attn16, *hmid16, *ffb, *w16;
    cudaGetSymbolAddress((void**)&h16, g_h16);
    cudaGetSymbolAddress((void**)&QKV16, g_QKV16);
    cudaGetSymbolAddress((void**)&dn, g_denom);
    cudaGetSymbolAddress((void**)&attn16, g_attn16);
    cudaGetSymbolAddress((void**)&hmid16, g_hmid16);
    cudaGetSymbolAddress((void**)&ffb, g_ff16);
    cudaGetSymbolAddress((void**)&w16, g_w16);

    static bool attr_done = false;
    if (!attr_done) {
        cudaFuncSetAttribute((const void*)gemm_h<2>, cudaFuncAttributeMaxDynamicSharedMemorySize, GEMM_SMEM_BYTES);
        cudaFuncSetAttribute((const void*)gemm_h<3>, cudaFuncAttributeMaxDynamicSharedMemorySize, GEMM_SMEM_BYTES);
        cudaFuncSetAttribute((const void*)gemm_ln<true, false, true>,   cudaFuncAttributeMaxDynamicSharedMemorySize, GEMMLN_SMEM_BYTES);
        cudaFuncSetAttribute((const void*)gemm_ln<false, true, false>,  cudaFuncAttributeMaxDynamicSharedMemorySize, GEMMLN_SMEM_BYTES);
        attr_done = true;
    }

    // 0. fused prologue: weight pack, h->fp16, attn16=0, denom=0
    prologue_kernel<<<(M_ * HID_ / 4) / 256, 256>>>(h, h16, attn16, dn,
                                                    Wq, Wk, Wv, Wo, ff1, ff2, w16);

    // 1. fused QKV projection -> fp16 QKV (3-stage occ-4 GEMM)
    dim3 gq(HID3 / TBN, M_ / TBM);             // (6, 512)
    gemm_h<3><<<gq, 256, GEMM_SMEM_BYTES>>>(h16, w16 + W16_QKV, nullptr, QKV16, HID_, HID3);

    // 2. fused edge pass: logits + exp + denom + fp16 scatter
    edge_attn_kernel<<<(B_ * E_) / 32, 256>>>(QKV16, ef, eidx, nE, We, dn, attn16);

    // 3. Wo GEMM (A = attn16 / denom, normalized in fill) + bias + residual(h)
    //    + LN1 fused -> hmid16 (fp16 only)
    dim3 gl(1, M_ / TBM);
    gemm_ln<true, false, true><<<gl, 256, GEMMLN_SMEM_BYTES>>>(
        attn16, w16 + W16_WO, bo, h, nullptr, ln1g, ln1b, nullptr, hmid16, dn, HID_);

    // 4. ff1 (+bias+relu -> fp16) (3-stage occ-4 GEMM)
    dim3 g2(2 * HID_ / TBN, M_ / TBM);         // (4, 512)
    gemm_h<2><<<g2, 256, GEMM_SMEM_BYTES>>>(hmid16, w16 + W16_FF1, b1, ffb, HID_, 2 * HID_);

    // 5. ff2 GEMM + bias + residual(hmid16) + LN2 fused -> out (fp32)
    gemm_ln<false, true, false><<<gl, 256, GEMMLN_SMEM_BYTES>>>(
        ffb, w16 + W16_FF2, b2, nullptr, hmid16, ln2g, ln2b, out, nullptr, nullptr, 2 * HID_);
}